// round 6
// baseline (speedup 1.0000x reference)
#include <cuda_runtime.h>
#include <math.h>

#define BB 8
#define NN 4096
#define WW 64
#define RR 4
#define EPSC 1e-8f

// ---------------- scratch (no allocs allowed -> __device__ globals) ----------
__device__ __align__(16) float g_usage[BB*NN];
__device__ __align__(16) float g_zw[BB*NN];
__device__ __align__(16) float g_alloc[BB*NN];
__device__ __align__(16) float g_ww[BB*NN];
__device__ __align__(16) float g_memnew[BB*NN*WW];
__device__ __align__(16) float g_zr[BB*NN*RR];
__device__ __align__(16) float g_cbr[BB*NN*RR];
__device__ __align__(16) float g_fwd[BB*NN*RR];
__device__ __align__(16) float g_bwd[BB*NN*RR];

// ---------------- K1: new usage + write content scores; zero d_out -----------
__global__ void k1_usage_sim(const float* __restrict__ memory,
                             const float* __restrict__ write_key,
                             const float* __restrict__ write_strength,
                             const float* __restrict__ free_gates,
                             const float* __restrict__ read_weightings,
                             const float* __restrict__ write_weighting,
                             const float* __restrict__ memory_usage,
                             float* __restrict__ out) {
    const int b   = blockIdx.y;
    const int tid = threadIdx.x;
    const int n   = blockIdx.x * 256 + tid;
    __shared__ float wk_s[WW];
    __shared__ float fg_s[RR];
    __shared__ float wkn;
    if (tid < WW) wk_s[tid] = write_key[b*WW + tid];
    if (tid < RR) fg_s[tid] = free_gates[b*RR + tid];
    if (blockIdx.y == 0 && blockIdx.x < 8) out[blockIdx.x*256 + tid] = 0.0f;
    __syncthreads();
    if (tid == 0) {
        float s = 0.f;
        for (int w = 0; w < WW; w++) s += wk_s[w]*wk_s[w];
        wkn = sqrtf(s);
    }
    __syncthreads();

    const size_t bn = (size_t)b*NN + n;
    float u  = memory_usage[bn];
    float wv = write_weighting[bn];
    float uw = u + wv - u*wv;
    float4 rw = *(const float4*)(read_weightings + bn*RR);
    float prod = (1.f - rw.x*fg_s[0]) * (1.f - rw.y*fg_s[1])
               * (1.f - rw.z*fg_s[2]) * (1.f - rw.w*fg_s[3]);
    g_usage[bn] = uw * prod;

    const float4* mrow = (const float4*)(memory + bn*WW);
    float dot = 0.f, nrm = 0.f;
    #pragma unroll
    for (int i = 0; i < 16; i++) {
        float4 m = mrow[i];
        dot += m.x*wk_s[i*4+0] + m.y*wk_s[i*4+1] + m.z*wk_s[i*4+2] + m.w*wk_s[i*4+3];
        nrm += m.x*m.x + m.y*m.y + m.z*m.z + m.w*m.w;
    }
    float sim = dot / (wkn * sqrtf(nrm) + EPSC);
    g_zw[bn] = write_strength[b] * sim;
}

// ---------------- K2: per-batch sort -> allocation weights -------------------
__global__ void k2_alloc() {
    const int b   = blockIdx.x;
    const int tid = threadIdx.x;  // 512 threads
    __shared__ float sv[NN];
    __shared__ int   si[NN];
    __shared__ float cp[512];

    for (int i = tid; i < NN; i += 512) { sv[i] = g_usage[(size_t)b*NN + i]; si[i] = i; }
    __syncthreads();

    for (int k = 2; k <= NN; k <<= 1) {
        for (int j = k >> 1; j > 0; j >>= 1) {
            for (int i = tid; i < NN; i += 512) {
                int ixj = i ^ j;
                if (ixj > i) {
                    bool up = ((i & k) == 0);
                    float a = sv[i], c = sv[ixj];
                    bool sw = up ? (a > c) : (a < c);
                    if (sw) {
                        sv[i] = c; sv[ixj] = a;
                        int t = si[i]; si[i] = si[ixj]; si[ixj] = t;
                    }
                }
            }
            __syncthreads();
        }
    }

    float p = 1.f;
    const int base = tid * 8;
    #pragma unroll
    for (int t = 0; t < 8; t++) p *= sv[base + t];
    cp[tid] = p;
    __syncthreads();
    for (int off = 1; off < 512; off <<= 1) {
        float v = cp[tid];
        float o = (tid >= off) ? cp[tid - off] : 1.f;
        __syncthreads();
        cp[tid] = v * o;
        __syncthreads();
    }
    float run = (tid == 0) ? 1.f : cp[tid - 1];
    #pragma unroll
    for (int t = 0; t < 8; t++) {
        float v = sv[base + t];
        g_alloc[(size_t)b*NN + si[base + t]] = (1.f - v) * run;
        run *= v;
    }
}

// ---------------- K3: softmax(cbw) + final ww; also zero g_fwd/g_bwd ---------
__global__ void k3_ww(const float* __restrict__ allocation_gate,
                      const float* __restrict__ write_gate) {
    const int b   = blockIdx.x;
    const int tid = threadIdx.x;  // 1024
    __shared__ float sh[32];
    const size_t bo = (size_t)b*NN;

    {
        float4 z4 = make_float4(0.f, 0.f, 0.f, 0.f);
        float4* f4 = (float4*)(g_fwd + bo*RR);
        float4* b4 = (float4*)(g_bwd + bo*RR);
        #pragma unroll
        for (int i = 0; i < 4; i++) { f4[tid + i*1024] = z4; b4[tid + i*1024] = z4; }
    }

    float z[4];
    float lm = -3.4e38f;
    #pragma unroll
    for (int k = 0; k < 4; k++) { z[k] = g_zw[bo + tid + k*1024]; lm = fmaxf(lm, z[k]); }
    for (int o = 16; o; o >>= 1) lm = fmaxf(lm, __shfl_xor_sync(0xffffffffu, lm, o));
    if ((tid & 31) == 0) sh[tid >> 5] = lm;
    __syncthreads();
    if (tid < 32) {
        float v = sh[tid];
        for (int o = 16; o; o >>= 1) v = fmaxf(v, __shfl_xor_sync(0xffffffffu, v, o));
        if (tid == 0) sh[0] = v;
    }
    __syncthreads();
    const float bmax = sh[0];
    __syncthreads();

    float e[4], ls = 0.f;
    #pragma unroll
    for (int k = 0; k < 4; k++) { e[k] = expf(z[k] - bmax); ls += e[k]; }
    for (int o = 16; o; o >>= 1) ls += __shfl_xor_sync(0xffffffffu, ls, o);
    if ((tid & 31) == 0) sh[tid >> 5] = ls;
    __syncthreads();
    if (tid < 32) {
        float v = sh[tid];
        for (int o = 16; o; o >>= 1) v += __shfl_xor_sync(0xffffffffu, v, o);
        if (tid == 0) sh[0] = v;
    }
    __syncthreads();
    const float bsum = sh[0];

    const float ag = allocation_gate[b], wg = write_gate[b];
    #pragma unroll
    for (int k = 0; k < 4; k++) {
        size_t idx = bo + tid + k*1024;
        float cbw = e[k] / bsum;
        g_ww[idx] = wg * (ag * g_alloc[idx] + (1.f - ag) * cbw);
    }
}

// ---------------- K4: memory erase/write + read content scores --------------
__global__ void k4_memupdate(const float* __restrict__ memory,
                             const float* __restrict__ erase_vector,
                             const float* __restrict__ write_vector,
                             const float* __restrict__ read_keys,
                             const float* __restrict__ read_strengths) {
    const int b   = blockIdx.y;
    const int tid = threadIdx.x;
    const int n   = blockIdx.x * 256 + tid;
    __shared__ float rk_s[WW][RR];
    __shared__ float ev_s[WW], wv_s[WW];
    __shared__ float nrk_s[RR], rs_s[RR];

    if (tid < WW) { ev_s[tid] = erase_vector[b*WW + tid]; wv_s[tid] = write_vector[b*WW + tid]; }
    { int w = tid >> 2, r = tid & 3; rk_s[w][r] = read_keys[b*WW*RR + tid]; }
    __syncthreads();
    if (tid < RR) {
        float s = 0.f;
        for (int w = 0; w < WW; w++) { float v = rk_s[w][tid]; s += v*v; }
        nrk_s[tid] = sqrtf(s);
        rs_s[tid]  = read_strengths[b*RR + tid];
    }
    __syncthreads();

    const size_t bn = (size_t)b*NN + n;
    const float wwn = g_ww[bn];
    const float4* mrow = (const float4*)(memory + bn*WW);
    float4* orow = (float4*)(g_memnew + bn*WW);

    float nrm = 0.f, s0 = 0.f, s1 = 0.f, s2 = 0.f, s3 = 0.f;
    #pragma unroll
    for (int i = 0; i < 16; i++) {
        float4 m = mrow[i];
        float mv[4] = {m.x, m.y, m.z, m.w};
        float ov[4];
        #pragma unroll
        for (int c = 0; c < 4; c++) {
            int w = i*4 + c;
            ov[c] = fmaf(mv[c], 1.f - wwn*ev_s[w], wwn*wv_s[w]);
            nrm += ov[c]*ov[c];
            s0 = fmaf(ov[c], rk_s[w][0], s0);
            s1 = fmaf(ov[c], rk_s[w][1], s1);
            s2 = fmaf(ov[c], rk_s[w][2], s2);
            s3 = fmaf(ov[c], rk_s[w][3], s3);
        }
        float4 o4 = make_float4(ov[0], ov[1], ov[2], ov[3]);
        orow[i] = o4;
    }
    const float nn = sqrtf(nrm);
    float4 zr;
    zr.x = rs_s[0]*s0 / (nn*nrk_s[0] + EPSC);
    zr.y = rs_s[1]*s1 / (nn*nrk_s[1] + EPSC);
    zr.z = rs_s[2]*s2 / (nn*nrk_s[2] + EPSC);
    zr.w = rs_s[3]*s3 / (nn*nrk_s[3] + EPSC);
    *(float4*)(g_zr + bn*RR) = zr;
}

// ---------------- K5: softmax(cbr) per (b,r) ---------------------------------
__global__ void k5_cbr() {
    const int r = blockIdx.x, b = blockIdx.y;
    const int tid = threadIdx.x;  // 256
    __shared__ float sh[8];
    const size_t bo = (size_t)b*NN;

    float z[16];
    float lm = -3.4e38f;
    #pragma unroll
    for (int k = 0; k < 16; k++) {
        size_t idx = (bo + tid + (size_t)k*256)*RR + r;
        z[k] = g_zr[idx];
        lm = fmaxf(lm, z[k]);
    }
    for (int o = 16; o; o >>= 1) lm = fmaxf(lm, __shfl_xor_sync(0xffffffffu, lm, o));
    if ((tid & 31) == 0) sh[tid >> 5] = lm;
    __syncthreads();
    if (tid < 8) {
        float v = sh[tid];
        for (int o = 4; o; o >>= 1) v = fmaxf(v, __shfl_xor_sync(0xffu, v, o));
        if (tid == 0) sh[0] = v;
    }
    __syncthreads();
    const float bmax = sh[0];
    __syncthreads();

    float ls = 0.f;
    #pragma unroll
    for (int k = 0; k < 16; k++) { z[k] = expf(z[k] - bmax); ls += z[k]; }
    for (int o = 16; o; o >>= 1) ls += __shfl_xor_sync(0xffffffffu, ls, o);
    if ((tid & 31) == 0) sh[tid >> 5] = ls;
    __syncthreads();
    if (tid < 8) {
        float v = sh[tid];
        for (int o = 4; o; o >>= 1) v += __shfl_xor_sync(0xffu, v, o);
        if (tid == 0) sh[0] = v;
    }
    __syncthreads();
    const float bsum = sh[0];

    #pragma unroll
    for (int k = 0; k < 16; k++) {
        size_t idx = (bo + tid + (size_t)k*256)*RR + r;
        g_cbr[idx] = z[k] / bsum;
    }
}

// ---------------- K6 v4: register-blocked, spill-free ------------------------
// a[n][m] = (1-ww_n-ww_m)*L[n][m] + ww_n*p_m, diag zeroed (never materialized)
// fwd[n,r] += a[n][m]*rwo[m,r]   ;   bwd[m,r] += a[n][m]*rwo[n,r]
// Thread patch: 4 rows x 4 cols per group (2 groups/chunk). bwd held in regs
// across all 256 rows. fwd reduced per group via 16-elem reduce-scatter.
#define K6_TM  128    // cols per block (32 lanes x 4)
#define K6_CH  64     // rows per chunk (8 warps x 8)
#define K6_NCH 4      // chunks -> 256 rows per block
__global__ void __launch_bounds__(256, 2) k6_link(const float* __restrict__ L,
                        const float* __restrict__ rwo,
                        const float* __restrict__ prec) {
    const int b    = blockIdx.z;
    const int m0   = blockIdx.x * K6_TM;
    const int n00  = blockIdx.y * (K6_CH * K6_NCH);
    const int tid  = threadIdx.x;     // 256
    const int warp = tid >> 5, lane = tid & 31;
    const size_t bo = (size_t)b * NN;
    const int mc   = m0 + lane * 4;   // this thread's 4 columns

    __shared__ float wwn_s[K6_CH];
    __shared__ __align__(16) float4 rn_s[K6_CH];
    __shared__ float bp_s[K6_TM][4];

    // per-thread column constants (held in regs for all 256 rows)
    const float4 wm4 = __ldg((const float4*)(g_ww + bo + mc));
    const float4 pm4 = __ldg((const float4*)(prec + bo + mc));
    float wm[4] = {wm4.x, wm4.y, wm4.z, wm4.w};
    float pm[4] = {pm4.x, pm4.y, pm4.z, pm4.w};
    float4 rm[4];
    #pragma unroll
    for (int c = 0; c < 4; c++) rm[c] = __ldg((const float4*)(rwo + (size_t)(bo + mc + c)*4));

    if (tid < K6_TM) { bp_s[tid][0]=0.f; bp_s[tid][1]=0.f; bp_s[tid][2]=0.f; bp_s[tid][3]=0.f; }

    float bacc[4][4] = {};   // bwd partials: this thread's 4 cols over all 256 rows

    for (int ch = 0; ch < K6_NCH; ch++) {
        const int n0 = n00 + ch * K6_CH;
        __syncthreads();
        if (tid < K6_CH) {
            wwn_s[tid] = g_ww[bo + n0 + tid];
            rn_s[tid]  = *(const float4*)(rwo + (size_t)(bo + n0 + tid)*4);
        }
        __syncthreads();
        const bool hd = (m0 < n0 + K6_CH) && (n0 < m0 + K6_TM);  // diag in range?

        #pragma unroll
        for (int g = 0; g < 2; g++) {
            const int rb = warp * 8 + g * 4;   // this group's 4 rows within chunk
            float4 lv[4];
            const float* Lb = L + (bo + n0 + rb) * (size_t)NN + mc;
            #pragma unroll
            for (int k = 0; k < 4; k++)
                lv[k] = __ldg((const float4*)(Lb + (size_t)k * NN));

            float v[16];   // fwd partials: v[row*4 + r]
            #pragma unroll
            for (int k = 0; k < 4; k++) {
                const int n   = n0 + rb + k;
                const float wwn = wwn_s[rb + k];
                const float A   = 1.f - wwn;
                const float4 rn = rn_s[rb + k];
                float a[4];
                a[0] = fmaf(lv[k].x, A - wm[0], wwn * pm[0]);
                a[1] = fmaf(lv[k].y, A - wm[1], wwn * pm[1]);
                a[2] = fmaf(lv[k].z, A - wm[2], wwn * pm[2]);
                a[3] = fmaf(lv[k].w, A - wm[3], wwn * pm[3]);
                if (hd) {
                    if (n == mc + 0) a[0] = 0.f;
                    if (n == mc + 1) a[1] = 0.f;
                    if (n == mc + 2) a[2] = 0.f;
                    if (n == mc + 3) a[3] = 0.f;
                }
                #pragma unroll
                for (int c = 0; c < 4; c++) {
                    bacc[c][0] = fmaf(a[c], rn.x, bacc[c][0]);
                    bacc[c][1] = fmaf(a[c], rn.y, bacc[c][1]);
                    bacc[c][2] = fmaf(a[c], rn.z, bacc[c][2]);
                    bacc[c][3] = fmaf(a[c], rn.w, bacc[c][3]);
                }
                v[k*4+0] = fmaf(a[3], rm[3].x, fmaf(a[2], rm[2].x, fmaf(a[1], rm[1].x, a[0]*rm[0].x)));
                v[k*4+1] = fmaf(a[3], rm[3].y, fmaf(a[2], rm[2].y, fmaf(a[1], rm[1].y, a[0]*rm[0].y)));
                v[k*4+2] = fmaf(a[3], rm[3].z, fmaf(a[2], rm[2].z, fmaf(a[1], rm[1].z, a[0]*rm[0].z)));
                v[k*4+3] = fmaf(a[3], rm[3].w, fmaf(a[2], rm[2].w, fmaf(a[1], rm[1].w, a[0]*rm[0].w)));
            }

            // fold upper half-warp (same 16 elem indices, other 16 columns)
            #pragma unroll
            for (int i = 0; i < 16; i++)
                v[i] += __shfl_xor_sync(0xffffffffu, v[i], 16);
            // reduce-scatter 16 elems across 16-lane halves: elem = lane & 15
            #pragma unroll
            for (int h = 8; h >= 1; h >>= 1) {
                const bool up = (lane & h) != 0;
                #pragma unroll
                for (int i = 0; i < h; i++) {
                    float send = up ? v[i] : v[i+h];
                    float recv = __shfl_xor_sync(0xffffffffu, send, h);
                    v[i] = (up ? v[i+h] : v[i]) + recv;
                }
            }
            // lanes 0..15 hold the reduced value for (row = rb + lane/4, r = lane%3)
            if (lane < 16)
                atomicAdd(g_fwd + (size_t)(bo + n0 + rb + (lane >> 2))*4 + (lane & 3), v[0]);
        }
    }

    // merge bwd partials: spread addresses within warp
    __syncthreads();
    #pragma unroll
    for (int c = 0; c < 4; c++) {
        float* dst = bp_s[lane*4 + c];
        atomicAdd(dst + 0, bacc[c][0]);
        atomicAdd(dst + 1, bacc[c][1]);
        atomicAdd(dst + 2, bacc[c][2]);
        atomicAdd(dst + 3, bacc[c][3]);
    }
    __syncthreads();
    if (tid < K6_TM) {
        float* dst = g_bwd + (size_t)(bo + m0 + tid)*4;
        atomicAdd(dst + 0, bp_s[tid][0]);
        atomicAdd(dst + 1, bp_s[tid][1]);
        atomicAdd(dst + 2, bp_s[tid][2]);
        atomicAdd(dst + 3, bp_s[tid][3]);
    }
}

// ---------------- K7: combine read modes + final bwr contraction -------------
__global__ void k7_read(const float* __restrict__ read_modes, float* __restrict__ out) {
    const int b   = blockIdx.y;
    const int n0  = blockIdx.x * 512;
    const int tid = threadIdx.x;          // 256
    const int w = tid & 63, r = tid >> 6;
    const size_t bo = (size_t)b * NN;
    __shared__ float rw_s[64][4];
    const int nl = tid >> 2, rr = tid & 3;
    const float mm0 = read_modes[b*12 + rr];
    const float mm1 = read_modes[b*12 + 4 + rr];
    const float mm2 = read_modes[b*12 + 8 + rr];

    float acc = 0.f;
    for (int c = 0; c < 512; c += 64) {
        size_t idx = (bo + n0 + c + nl)*4 + rr;
        float rwv = mm0*g_bwd[idx] + mm1*g_cbr[idx] + mm2*g_fwd[idx];
        __syncthreads();
        rw_s[nl][rr] = rwv;
        __syncthreads();
        const float* mp = g_memnew + (bo + n0 + c)*WW + w;
        #pragma unroll 8
        for (int q = 0; q < 64; q++)
            acc = fmaf(mp[(size_t)q*WW], rw_s[q][r], acc);
    }
    atomicAdd(&out[b*WW*RR + w*RR + r], acc);
}

// ---------------- launch -----------------------------------------------------
extern "C" void kernel_launch(void* const* d_in, const int* in_sizes, int n_in,
                              void* d_out, int out_size) {
    const float* erase_vector    = (const float*)d_in[0];
    const float* free_gates      = (const float*)d_in[1];
    const float* allocation_gate = (const float*)d_in[2];
    const float* write_gate      = (const float*)d_in[3];
    const float* read_modes      = (const float*)d_in[4];
    const float* read_strengths  = (const float*)d_in[5];
    const float* read_keys       = (const float*)d_in[6];
    const float* write_vector    = (const float*)d_in[7];
    const float* write_key       = (const float*)d_in[8];
    const float* write_strength  = (const float*)d_in[9];
    const float* memory          = (const float*)d_in[10];
    const float* read_weightings = (const float*)d_in[11];
    const float* write_weighting = (const float*)d_in[12];
    const float* memory_usage    = (const float*)d_in[13];
    const float* link_matrix     = (const float*)d_in[14];
    const float* precedence      = (const float*)d_in[15];
    float* out = (float*)d_out;

    k1_usage_sim<<<dim3(16, 8), 256>>>(memory, write_key, write_strength, free_gates,
                                       read_weightings, write_weighting, memory_usage, out);
    k2_alloc<<<8, 512>>>();
    k3_ww<<<8, 1024>>>(allocation_gate, write_gate);
    // k6 at launch index 3 so ncu's fixed-skip capture lands on it
    k6_link<<<dim3(NN/K6_TM, NN/(K6_CH*K6_NCH), BB), 256>>>(link_matrix, read_weightings, precedence);
    k4_memupdate<<<dim3(16, 8), 256>>>(memory, erase_vector, write_vector,
                                       read_keys, read_strengths);
    k5_cbr<<<dim3(4, 8), 256>>>();
    k7_read<<<dim3(8, 8), 256>>>(read_modes, out);
}

// round 7
// speedup vs baseline: 1.1284x; 1.1284x over previous
#include <cuda_runtime.h>
#include <math.h>

#define BB 8
#define NN 4096
#define WW 64
#define RR 4
#define EPSC 1e-8f

// ---------------- scratch (no allocs allowed -> __device__ globals) ----------
__device__ __align__(16) float g_usage[BB*NN];
__device__ __align__(16) float g_zw[BB*NN];
__device__ __align__(16) float g_alloc[BB*NN];
__device__ __align__(16) float g_ww[BB*NN];
__device__ __align__(16) float g_memnew[BB*NN*WW];
__device__ __align__(16) float g_zr[BB*NN*RR];
__device__ __align__(16) float g_cbr[BB*NN*RR];
__device__ __align__(16) float g_fwd[BB*NN*RR];
__device__ __align__(16) float g_bwd[BB*NN*RR];

// ---------------- K1: new usage + write content scores; zero d_out -----------
__global__ void k1_usage_sim(const float* __restrict__ memory,
                             const float* __restrict__ write_key,
                             const float* __restrict__ write_strength,
                             const float* __restrict__ free_gates,
                             const float* __restrict__ read_weightings,
                             const float* __restrict__ write_weighting,
                             const float* __restrict__ memory_usage,
                             float* __restrict__ out) {
    const int b   = blockIdx.y;
    const int tid = threadIdx.x;
    const int n   = blockIdx.x * 256 + tid;
    __shared__ float wk_s[WW];
    __shared__ float fg_s[RR];
    __shared__ float wkn;
    if (tid < WW) wk_s[tid] = write_key[b*WW + tid];
    if (tid < RR) fg_s[tid] = free_gates[b*RR + tid];
    if (blockIdx.y == 0 && blockIdx.x < 8) out[blockIdx.x*256 + tid] = 0.0f;
    __syncthreads();
    if (tid == 0) {
        float s = 0.f;
        for (int w = 0; w < WW; w++) s += wk_s[w]*wk_s[w];
        wkn = sqrtf(s);
    }
    __syncthreads();

    const size_t bn = (size_t)b*NN + n;
    float u  = memory_usage[bn];
    float wv = write_weighting[bn];
    float uw = u + wv - u*wv;
    float4 rw = *(const float4*)(read_weightings + bn*RR);
    float prod = (1.f - rw.x*fg_s[0]) * (1.f - rw.y*fg_s[1])
               * (1.f - rw.z*fg_s[2]) * (1.f - rw.w*fg_s[3]);
    g_usage[bn] = uw * prod;

    const float4* mrow = (const float4*)(memory + bn*WW);
    float dot = 0.f, nrm = 0.f;
    #pragma unroll
    for (int i = 0; i < 16; i++) {
        float4 m = mrow[i];
        dot += m.x*wk_s[i*4+0] + m.y*wk_s[i*4+1] + m.z*wk_s[i*4+2] + m.w*wk_s[i*4+3];
        nrm += m.x*m.x + m.y*m.y + m.z*m.z + m.w*m.w;
    }
    float sim = dot / (wkn * sqrtf(nrm) + EPSC);
    g_zw[bn] = write_strength[b] * sim;
}

// ---------------- K2: per-batch sort -> allocation weights (1024 thr) --------
__global__ void k2_alloc() {
    const int b   = blockIdx.x;
    const int tid = threadIdx.x;  // 1024 threads
    __shared__ float sv[NN];
    __shared__ int   si[NN];
    __shared__ float cp[1024];

    for (int i = tid; i < NN; i += 1024) { sv[i] = g_usage[(size_t)b*NN + i]; si[i] = i; }
    __syncthreads();

    for (int k = 2; k <= NN; k <<= 1) {
        for (int j = k >> 1; j > 0; j >>= 1) {
            for (int i = tid; i < NN; i += 1024) {
                int ixj = i ^ j;
                if (ixj > i) {
                    bool up = ((i & k) == 0);
                    float a = sv[i], c = sv[ixj];
                    bool sw = up ? (a > c) : (a < c);
                    if (sw) {
                        sv[i] = c; sv[ixj] = a;
                        int t = si[i]; si[i] = si[ixj]; si[ixj] = t;
                    }
                }
            }
            __syncthreads();
        }
    }

    // chunked exclusive prefix product of sorted usage (4 per thread)
    float p = 1.f;
    const int base = tid * 4;
    #pragma unroll
    for (int t = 0; t < 4; t++) p *= sv[base + t];
    cp[tid] = p;
    __syncthreads();
    for (int off = 1; off < 1024; off <<= 1) {
        float v = cp[tid];
        float o = (tid >= off) ? cp[tid - off] : 1.f;
        __syncthreads();
        cp[tid] = v * o;
        __syncthreads();
    }
    float run = (tid == 0) ? 1.f : cp[tid - 1];
    #pragma unroll
    for (int t = 0; t < 4; t++) {
        float v = sv[base + t];
        g_alloc[(size_t)b*NN + si[base + t]] = (1.f - v) * run;
        run *= v;
    }
}

// ---------------- K3: softmax(cbw) + final ww; also zero g_fwd/g_bwd ---------
__global__ void k3_ww(const float* __restrict__ allocation_gate,
                      const float* __restrict__ write_gate) {
    const int b   = blockIdx.x;
    const int tid = threadIdx.x;  // 1024
    __shared__ float sh[32];
    const size_t bo = (size_t)b*NN;

    {
        float4 z4 = make_float4(0.f, 0.f, 0.f, 0.f);
        float4* f4 = (float4*)(g_fwd + bo*RR);
        float4* b4 = (float4*)(g_bwd + bo*RR);
        #pragma unroll
        for (int i = 0; i < 4; i++) { f4[tid + i*1024] = z4; b4[tid + i*1024] = z4; }
    }

    float z[4];
    float lm = -3.4e38f;
    #pragma unroll
    for (int k = 0; k < 4; k++) { z[k] = g_zw[bo + tid + k*1024]; lm = fmaxf(lm, z[k]); }
    for (int o = 16; o; o >>= 1) lm = fmaxf(lm, __shfl_xor_sync(0xffffffffu, lm, o));
    if ((tid & 31) == 0) sh[tid >> 5] = lm;
    __syncthreads();
    if (tid < 32) {
        float v = sh[tid];
        for (int o = 16; o; o >>= 1) v = fmaxf(v, __shfl_xor_sync(0xffffffffu, v, o));
        if (tid == 0) sh[0] = v;
    }
    __syncthreads();
    const float bmax = sh[0];
    __syncthreads();

    float e[4], ls = 0.f;
    #pragma unroll
    for (int k = 0; k < 4; k++) { e[k] = expf(z[k] - bmax); ls += e[k]; }
    for (int o = 16; o; o >>= 1) ls += __shfl_xor_sync(0xffffffffu, ls, o);
    if ((tid & 31) == 0) sh[tid >> 5] = ls;
    __syncthreads();
    if (tid < 32) {
        float v = sh[tid];
        for (int o = 16; o; o >>= 1) v += __shfl_xor_sync(0xffffffffu, v, o);
        if (tid == 0) sh[0] = v;
    }
    __syncthreads();
    const float bsum = sh[0];

    const float ag = allocation_gate[b], wg = write_gate[b];
    #pragma unroll
    for (int k = 0; k < 4; k++) {
        size_t idx = bo + tid + k*1024;
        float cbw = e[k] / bsum;
        g_ww[idx] = wg * (ag * g_alloc[idx] + (1.f - ag) * cbw);
    }
}

// ---------------- K4: memory erase/write + read content scores --------------
__global__ void k4_memupdate(const float* __restrict__ memory,
                             const float* __restrict__ erase_vector,
                             const float* __restrict__ write_vector,
                             const float* __restrict__ read_keys,
                             const float* __restrict__ read_strengths) {
    const int b   = blockIdx.y;
    const int tid = threadIdx.x;
    const int n   = blockIdx.x * 256 + tid;
    __shared__ float rk_s[WW][RR];
    __shared__ float ev_s[WW], wv_s[WW];
    __shared__ float nrk_s[RR], rs_s[RR];

    if (tid < WW) { ev_s[tid] = erase_vector[b*WW + tid]; wv_s[tid] = write_vector[b*WW + tid]; }
    { int w = tid >> 2, r = tid & 3; rk_s[w][r] = read_keys[b*WW*RR + tid]; }
    __syncthreads();
    if (tid < RR) {
        float s = 0.f;
        for (int w = 0; w < WW; w++) { float v = rk_s[w][tid]; s += v*v; }
        nrk_s[tid] = sqrtf(s);
        rs_s[tid]  = read_strengths[b*RR + tid];
    }
    __syncthreads();

    const size_t bn = (size_t)b*NN + n;
    const float wwn = g_ww[bn];
    const float4* mrow = (const float4*)(memory + bn*WW);
    float4* orow = (float4*)(g_memnew + bn*WW);

    float nrm = 0.f, s0 = 0.f, s1 = 0.f, s2 = 0.f, s3 = 0.f;
    #pragma unroll
    for (int i = 0; i < 16; i++) {
        float4 m = mrow[i];
        float mv[4] = {m.x, m.y, m.z, m.w};
        float ov[4];
        #pragma unroll
        for (int c = 0; c < 4; c++) {
            int w = i*4 + c;
            ov[c] = fmaf(mv[c], 1.f - wwn*ev_s[w], wwn*wv_s[w]);
            nrm += ov[c]*ov[c];
            s0 = fmaf(ov[c], rk_s[w][0], s0);
            s1 = fmaf(ov[c], rk_s[w][1], s1);
            s2 = fmaf(ov[c], rk_s[w][2], s2);
            s3 = fmaf(ov[c], rk_s[w][3], s3);
        }
        float4 o4 = make_float4(ov[0], ov[1], ov[2], ov[3]);
        orow[i] = o4;
    }
    const float nn = sqrtf(nrm);
    float4 zr;
    zr.x = rs_s[0]*s0 / (nn*nrk_s[0] + EPSC);
    zr.y = rs_s[1]*s1 / (nn*nrk_s[1] + EPSC);
    zr.z = rs_s[2]*s2 / (nn*nrk_s[2] + EPSC);
    zr.w = rs_s[3]*s3 / (nn*nrk_s[3] + EPSC);
    *(float4*)(g_zr + bn*RR) = zr;
}

// ---------------- K5: softmax(cbr) per (b,r) ---------------------------------
__global__ void k5_cbr() {
    const int r = blockIdx.x, b = blockIdx.y;
    const int tid = threadIdx.x;  // 256
    __shared__ float sh[8];
    const size_t bo = (size_t)b*NN;

    float z[16];
    float lm = -3.4e38f;
    #pragma unroll
    for (int k = 0; k < 16; k++) {
        size_t idx = (bo + tid + (size_t)k*256)*RR + r;
        z[k] = g_zr[idx];
        lm = fmaxf(lm, z[k]);
    }
    for (int o = 16; o; o >>= 1) lm = fmaxf(lm, __shfl_xor_sync(0xffffffffu, lm, o));
    if ((tid & 31) == 0) sh[tid >> 5] = lm;
    __syncthreads();
    if (tid < 8) {
        float v = sh[tid];
        for (int o = 4; o; o >>= 1) v = fmaxf(v, __shfl_xor_sync(0xffu, v, o));
        if (tid == 0) sh[0] = v;
    }
    __syncthreads();
    const float bmax = sh[0];
    __syncthreads();

    float ls = 0.f;
    #pragma unroll
    for (int k = 0; k < 16; k++) { z[k] = expf(z[k] - bmax); ls += z[k]; }
    for (int o = 16; o; o >>= 1) ls += __shfl_xor_sync(0xffffffffu, ls, o);
    if ((tid & 31) == 0) sh[tid >> 5] = ls;
    __syncthreads();
    if (tid < 8) {
        float v = sh[tid];
        for (int o = 4; o; o >>= 1) v += __shfl_xor_sync(0xffu, v, o);
        if (tid == 0) sh[0] = v;
    }
    __syncthreads();
    const float bsum = sh[0];

    #pragma unroll
    for (int k = 0; k < 16; k++) {
        size_t idx = (bo + tid + (size_t)k*256)*RR + r;
        g_cbr[idx] = z[k] / bsum;
    }
}

// ---------------- K6 v5: 2 cols/thread, spill-free, no diag in hot loop ------
// a[n][m] = (1-ww_n-ww_m)*L[n][m] + ww_n*p_m  (diag NOT zeroed here; the
// m==n term is subtracted analytically in K7).
// fwd[n,r] += a[n][m]*rwo[m,r]   ;   bwd[m,r] += a[n][m]*rwo[n,r]
#define K6_TM  64     // cols per block (32 lanes x 2)
#define K6_CH  64     // rows per chunk (8 warps x 8)
#define K6_NCH 4      // chunks -> 256 rows per block
__global__ void __launch_bounds__(256, 2) k6_link(const float* __restrict__ L,
                        const float* __restrict__ rwo,
                        const float* __restrict__ prec) {
    const int b    = blockIdx.z;
    const int m0   = blockIdx.x * K6_TM;
    const int n00  = blockIdx.y * (K6_CH * K6_NCH);
    const int tid  = threadIdx.x;     // 256
    const int warp = tid >> 5, lane = tid & 31;
    const size_t bo = (size_t)b * NN;
    const int mc   = m0 + lane * 2;   // this thread's 2 columns

    __shared__ float wwn_s[K6_CH];
    __shared__ __align__(16) float4 rn_s[K6_CH];
    __shared__ __align__(16) float bw_s[8][K6_TM][4];   // per-warp bwd slabs

    // per-thread column constants
    const float2 wm = *(const float2*)(g_ww + bo + mc);
    const float2 pm = *(const float2*)(prec + bo + mc);
    const float4 rm0 = __ldg((const float4*)(rwo + (size_t)(bo + mc + 0)*4));
    const float4 rm1 = __ldg((const float4*)(rwo + (size_t)(bo + mc + 1)*4));

    float bacc[2][4] = {};   // bwd partials: this thread's 2 cols over 256 rows

    for (int ch = 0; ch < K6_NCH; ch++) {
        const int n0 = n00 + ch * K6_CH;
        __syncthreads();
        if (tid < K6_CH) {
            wwn_s[tid] = g_ww[bo + n0 + tid];
            rn_s[tid]  = *(const float4*)(rwo + (size_t)(bo + n0 + tid)*4);
        }
        __syncthreads();

        #pragma unroll
        for (int g = 0; g < 2; g++) {
            const int rb = warp * 8 + g * 4;   // this group's 4 rows
            float2 lv[4];
            const float* Lb = L + (bo + n0 + rb) * (size_t)NN + mc;
            #pragma unroll
            for (int k = 0; k < 4; k++)
                lv[k] = __ldg((const float2*)(Lb + (size_t)k * NN));

            float v[16];   // fwd partials: v[row*4 + r]
            #pragma unroll
            for (int k = 0; k < 4; k++) {
                const float wwn = wwn_s[rb + k];
                const float A   = 1.f - wwn;
                const float4 rn = rn_s[rb + k];
                const float a0 = fmaf(lv[k].x, A - wm.x, wwn * pm.x);
                const float a1 = fmaf(lv[k].y, A - wm.y, wwn * pm.y);
                bacc[0][0] = fmaf(a0, rn.x, bacc[0][0]);
                bacc[0][1] = fmaf(a0, rn.y, bacc[0][1]);
                bacc[0][2] = fmaf(a0, rn.z, bacc[0][2]);
                bacc[0][3] = fmaf(a0, rn.w, bacc[0][3]);
                bacc[1][0] = fmaf(a1, rn.x, bacc[1][0]);
                bacc[1][1] = fmaf(a1, rn.y, bacc[1][1]);
                bacc[1][2] = fmaf(a1, rn.z, bacc[1][2]);
                bacc[1][3] = fmaf(a1, rn.w, bacc[1][3]);
                v[k*4+0] = fmaf(a1, rm1.x, a0 * rm0.x);
                v[k*4+1] = fmaf(a1, rm1.y, a0 * rm0.y);
                v[k*4+2] = fmaf(a1, rm1.z, a0 * rm0.z);
                v[k*4+3] = fmaf(a1, rm1.w, a0 * rm0.w);
            }

            // fold upper half-warp, then 16-elem reduce-scatter (elem = lane&15)
            #pragma unroll
            for (int i = 0; i < 16; i++)
                v[i] += __shfl_xor_sync(0xffffffffu, v[i], 16);
            #pragma unroll
            for (int h = 8; h >= 1; h >>= 1) {
                const bool up = (lane & h) != 0;
                #pragma unroll
                for (int i = 0; i < h; i++) {
                    float send = up ? v[i] : v[i+h];
                    float recv = __shfl_xor_sync(0xffffffffu, send, h);
                    v[i] = (up ? v[i+h] : v[i]) + recv;
                }
            }
            if (lane < 16)
                atomicAdd(g_fwd + (size_t)(bo + n0 + rb + (lane >> 2))*4 + (lane & 3), v[0]);
        }
    }

    // bwd merge: plain per-warp stores (STS.128), then tree add + one RED each
    __syncthreads();
    *(float4*)&bw_s[warp][lane*2 + 0][0] = make_float4(bacc[0][0], bacc[0][1], bacc[0][2], bacc[0][3]);
    *(float4*)&bw_s[warp][lane*2 + 1][0] = make_float4(bacc[1][0], bacc[1][1], bacc[1][2], bacc[1][3]);
    __syncthreads();
    {
        const int col = tid >> 2, r = tid & 3;   // 256 threads = 64 cols x 4 r
        float s = bw_s[0][col][r] + bw_s[1][col][r] + bw_s[2][col][r] + bw_s[3][col][r]
                + bw_s[4][col][r] + bw_s[5][col][r] + bw_s[6][col][r] + bw_s[7][col][r];
        atomicAdd(g_bwd + (size_t)(bo + m0 + col)*4 + r, s);
    }
}

// ---------------- K7: combine read modes (+ diag correction) + bwr -----------
__global__ void k7_read(const float* __restrict__ read_modes,
                        const float* __restrict__ L,
                        const float* __restrict__ prec,
                        const float* __restrict__ rwo,
                        float* __restrict__ out) {
    const int b   = blockIdx.y;
    const int n0  = blockIdx.x * 512;
    const int tid = threadIdx.x;          // 256
    const int w = tid & 63, r = tid >> 6;
    const size_t bo = (size_t)b * NN;
    __shared__ float rw_s[64][4];
    const int nl = tid >> 2, rr = tid & 3;
    const float mm0 = read_modes[b*12 + rr];
    const float mm1 = read_modes[b*12 + 4 + rr];
    const float mm2 = read_modes[b*12 + 8 + rr];

    float acc = 0.f;
    for (int c = 0; c < 512; c += 64) {
        const int n = n0 + c + nl;
        size_t idx = (bo + n)*4 + rr;
        // diag correction: a_nn = (1-2ww_n)L[n,n] + ww_n p_n ; subtract a_nn*rwo[n,r]
        const float Lnn = L[(bo + n)*(size_t)NN + n];
        const float wwn = g_ww[bo + n];
        const float ann = fmaf(1.f - 2.f*wwn, Lnn, wwn * prec[bo + n]);
        const float corr = ann * rwo[idx];
        float rwv = mm0*(g_bwd[idx] - corr) + mm1*g_cbr[idx] + mm2*(g_fwd[idx] - corr);
        __syncthreads();
        rw_s[nl][rr] = rwv;
        __syncthreads();
        const float* mp = g_memnew + (bo + n0 + c)*WW + w;
        #pragma unroll 8
        for (int q = 0; q < 64; q++)
            acc = fmaf(mp[(size_t)q*WW], rw_s[q][r], acc);
    }
    atomicAdd(&out[b*WW*RR + w*RR + r], acc);
}

// ---------------- launch -----------------------------------------------------
extern "C" void kernel_launch(void* const* d_in, const int* in_sizes, int n_in,
                              void* d_out, int out_size) {
    const float* erase_vector    = (const float*)d_in[0];
    const float* free_gates      = (const float*)d_in[1];
    const float* allocation_gate = (const float*)d_in[2];
    const float* write_gate      = (const float*)d_in[3];
    const float* read_modes      = (const float*)d_in[4];
    const float* read_strengths  = (const float*)d_in[5];
    const float* read_keys       = (const float*)d_in[6];
    const float* write_vector    = (const float*)d_in[7];
    const float* write_key       = (const float*)d_in[8];
    const float* write_strength  = (const float*)d_in[9];
    const float* memory          = (const float*)d_in[10];
    const float* read_weightings = (const float*)d_in[11];
    const float* write_weighting = (const float*)d_in[12];
    const float* memory_usage    = (const float*)d_in[13];
    const float* link_matrix     = (const float*)d_in[14];
    const float* precedence      = (const float*)d_in[15];
    float* out = (float*)d_out;

    k1_usage_sim<<<dim3(16, 8), 256>>>(memory, write_key, write_strength, free_gates,
                                       read_weightings, write_weighting, memory_usage, out);
    k2_alloc<<<8, 1024>>>();
    k3_ww<<<8, 1024>>>(allocation_gate, write_gate);
    // k6 at launch index 3 so ncu's fixed-skip capture lands on it
    k6_link<<<dim3(NN/K6_TM, NN/(K6_CH*K6_NCH), BB), 256>>>(link_matrix, read_weightings, precedence);
    k4_memupdate<<<dim3(16, 8), 256>>>(memory, erase_vector, write_vector,
                                       read_keys, read_strengths);
    k5_cbr<<<dim3(4, 8), 256>>>();
    k7_read<<<dim3(8, 8), 256>>>(read_modes, link_matrix, precedence, read_weightings, out);
}

// round 10
// speedup vs baseline: 1.1740x; 1.0404x over previous
#include <cuda_runtime.h>
#include <math.h>

#define BB 8
#define NN 4096
#define WW 64
#define RR 4
#define EPSC 1e-8f

typedef unsigned long long u64;

// ---- f32x2 packed helpers (sm_103a) -----------------------------------------
__device__ __forceinline__ u64 pack2(float lo, float hi) {
    u64 r; asm("mov.b64 %0, {%1, %2};" : "=l"(r) : "f"(lo), "f"(hi)); return r;
}
__device__ __forceinline__ void unpack2(float& lo, float& hi, u64 v) {
    asm("mov.b64 {%0, %1}, %2;" : "=f"(lo), "=f"(hi) : "l"(v));
}
__device__ __forceinline__ u64 fma2(u64 a, u64 b, u64 c) {
    u64 d; asm("fma.rn.f32x2 %0, %1, %2, %3;" : "=l"(d) : "l"(a), "l"(b), "l"(c)); return d;
}
__device__ __forceinline__ u64 add2(u64 a, u64 b) {
    u64 d; asm("add.rn.f32x2 %0, %1, %2;" : "=l"(d) : "l"(a), "l"(b)); return d;
}
__device__ __forceinline__ u64 mul2(u64 a, u64 b) {
    u64 d; asm("mul.rn.f32x2 %0, %1, %2;" : "=l"(d) : "l"(a), "l"(b)); return d;
}

// ---------------- scratch (no allocs allowed -> __device__ globals) ----------
__device__ __align__(16) float g_usage[BB*NN];
__device__ __align__(16) float g_zw[BB*NN];
__device__ __align__(16) float g_alloc[BB*NN];
__device__ __align__(16) float g_ww[BB*NN];
__device__ __align__(16) float g_memnew[BB*NN*WW];
__device__ __align__(16) float g_zr[BB*NN*RR];
__device__ __align__(16) float g_cbr[BB*NN*RR];
__device__ __align__(16) float g_fwd[BB*NN*RR];
__device__ __align__(16) float g_bwd[BB*NN*RR];

// ---------------- K1: new usage + write content scores; zero d_out -----------
__global__ void k1_usage_sim(const float* __restrict__ memory,
                             const float* __restrict__ write_key,
                             const float* __restrict__ write_strength,
                             const float* __restrict__ free_gates,
                             const float* __restrict__ read_weightings,
                             const float* __restrict__ write_weighting,
                             const float* __restrict__ memory_usage,
                             float* __restrict__ out) {
    const int b   = blockIdx.y;
    const int tid = threadIdx.x;
    const int n   = blockIdx.x * 256 + tid;
    __shared__ float wk_s[WW];
    __shared__ float fg_s[RR];
    __shared__ float wkn;
    if (tid < WW) wk_s[tid] = write_key[b*WW + tid];
    if (tid < RR) fg_s[tid] = free_gates[b*RR + tid];
    if (blockIdx.y == 0 && blockIdx.x < 8) out[blockIdx.x*256 + tid] = 0.0f;
    __syncthreads();
    if (tid == 0) {
        float s = 0.f;
        for (int w = 0; w < WW; w++) s += wk_s[w]*wk_s[w];
        wkn = sqrtf(s);
    }
    __syncthreads();

    const size_t bn = (size_t)b*NN + n;
    float u  = memory_usage[bn];
    float wv = write_weighting[bn];
    float uw = u + wv - u*wv;
    float4 rw = *(const float4*)(read_weightings + bn*RR);
    float prod = (1.f - rw.x*fg_s[0]) * (1.f - rw.y*fg_s[1])
               * (1.f - rw.z*fg_s[2]) * (1.f - rw.w*fg_s[3]);
    g_usage[bn] = uw * prod;

    const float4* mrow = (const float4*)(memory + bn*WW);
    float dot = 0.f, nrm = 0.f;
    #pragma unroll
    for (int i = 0; i < 16; i++) {
        float4 m = mrow[i];
        dot += m.x*wk_s[i*4+0] + m.y*wk_s[i*4+1] + m.z*wk_s[i*4+2] + m.w*wk_s[i*4+3];
        nrm += m.x*m.x + m.y*m.y + m.z*m.z + m.w*m.w;
    }
    float sim = dot / (wkn * sqrtf(nrm) + EPSC);
    g_zw[bn] = write_strength[b] * sim;
}

// ---------------- K2: per-batch sort -> allocation weights (1024 thr) --------
__global__ void k2_alloc() {
    const int b   = blockIdx.x;
    const int tid = threadIdx.x;  // 1024 threads
    __shared__ float sv[NN];
    __shared__ int   si[NN];
    __shared__ float cp[1024];

    for (int i = tid; i < NN; i += 1024) { sv[i] = g_usage[(size_t)b*NN + i]; si[i] = i; }
    __syncthreads();

    for (int k = 2; k <= NN; k <<= 1) {
        for (int j = k >> 1; j > 0; j >>= 1) {
            for (int i = tid; i < NN; i += 1024) {
                int ixj = i ^ j;
                if (ixj > i) {
                    bool up = ((i & k) == 0);
                    float a = sv[i], c = sv[ixj];
                    bool sw = up ? (a > c) : (a < c);
                    if (sw) {
                        sv[i] = c; sv[ixj] = a;
                        int t = si[i]; si[i] = si[ixj]; si[ixj] = t;
                    }
                }
            }
            __syncthreads();
        }
    }

    float p = 1.f;
    const int base = tid * 4;
    #pragma unroll
    for (int t = 0; t < 4; t++) p *= sv[base + t];
    cp[tid] = p;
    __syncthreads();
    for (int off = 1; off < 1024; off <<= 1) {
        float v = cp[tid];
        float o = (tid >= off) ? cp[tid - off] : 1.f;
        __syncthreads();
        cp[tid] = v * o;
        __syncthreads();
    }
    float run = (tid == 0) ? 1.f : cp[tid - 1];
    #pragma unroll
    for (int t = 0; t < 4; t++) {
        float v = sv[base + t];
        g_alloc[(size_t)b*NN + si[base + t]] = (1.f - v) * run;
        run *= v;
    }
}

// ---------------- K3: softmax(cbw) + final ww; also zero g_fwd/g_bwd ---------
__global__ void k3_ww(const float* __restrict__ allocation_gate,
                      const float* __restrict__ write_gate) {
    const int b   = blockIdx.x;
    const int tid = threadIdx.x;  // 1024
    __shared__ float sh[32];
    const size_t bo = (size_t)b*NN;

    {
        float4 z4 = make_float4(0.f, 0.f, 0.f, 0.f);
        float4* f4 = (float4*)(g_fwd + bo*RR);
        float4* b4 = (float4*)(g_bwd + bo*RR);
        #pragma unroll
        for (int i = 0; i < 4; i++) { f4[tid + i*1024] = z4; b4[tid + i*1024] = z4; }
    }

    float z[4];
    float lm = -3.4e38f;
    #pragma unroll
    for (int k = 0; k < 4; k++) { z[k] = g_zw[bo + tid + k*1024]; lm = fmaxf(lm, z[k]); }
    for (int o = 16; o; o >>= 1) lm = fmaxf(lm, __shfl_xor_sync(0xffffffffu, lm, o));
    if ((tid & 31) == 0) sh[tid >> 5] = lm;
    __syncthreads();
    if (tid < 32) {
        float v = sh[tid];
        for (int o = 16; o; o >>= 1) v = fmaxf(v, __shfl_xor_sync(0xffffffffu, v, o));
        if (tid == 0) sh[0] = v;
    }
    __syncthreads();
    const float bmax = sh[0];
    __syncthreads();

    float e[4], ls = 0.f;
    #pragma unroll
    for (int k = 0; k < 4; k++) { e[k] = expf(z[k] - bmax); ls += e[k]; }
    for (int o = 16; o; o >>= 1) ls += __shfl_xor_sync(0xffffffffu, ls, o);
    if ((tid & 31) == 0) sh[tid >> 5] = ls;
    __syncthreads();
    if (tid < 32) {
        float v = sh[tid];
        for (int o = 16; o; o >>= 1) v += __shfl_xor_sync(0xffffffffu, v, o);
        if (tid == 0) sh[0] = v;
    }
    __syncthreads();
    const float bsum = sh[0];

    const float ag = allocation_gate[b], wg = write_gate[b];
    #pragma unroll
    for (int k = 0; k < 4; k++) {
        size_t idx = bo + tid + k*1024;
        float cbw = e[k] / bsum;
        g_ww[idx] = wg * (ag * g_alloc[idx] + (1.f - ag) * cbw);
    }
}

// ---------------- K4: memory erase/write + read content scores --------------
__global__ void k4_memupdate(const float* __restrict__ memory,
                             const float* __restrict__ erase_vector,
                             const float* __restrict__ write_vector,
                             const float* __restrict__ read_keys,
                             const float* __restrict__ read_strengths) {
    const int b   = blockIdx.y;
    const int tid = threadIdx.x;
    const int n   = blockIdx.x * 256 + tid;
    __shared__ float rk_s[WW][RR];
    __shared__ float ev_s[WW], wv_s[WW];
    __shared__ float nrk_s[RR], rs_s[RR];

    if (tid < WW) { ev_s[tid] = erase_vector[b*WW + tid]; wv_s[tid] = write_vector[b*WW + tid]; }
    { int w = tid >> 2, r = tid & 3; rk_s[w][r] = read_keys[b*WW*RR + tid]; }
    __syncthreads();
    if (tid < RR) {
        float s = 0.f;
        for (int w = 0; w < WW; w++) { float v = rk_s[w][tid]; s += v*v; }
        nrk_s[tid] = sqrtf(s);
        rs_s[tid]  = read_strengths[b*RR + tid];
    }
    __syncthreads();

    const size_t bn = (size_t)b*NN + n;
    const float wwn = g_ww[bn];
    const float4* mrow = (const float4*)(memory + bn*WW);
    float4* orow = (float4*)(g_memnew + bn*WW);

    float nrm = 0.f, s0 = 0.f, s1 = 0.f, s2 = 0.f, s3 = 0.f;
    #pragma unroll
    for (int i = 0; i < 16; i++) {
        float4 m = mrow[i];
        float mv[4] = {m.x, m.y, m.z, m.w};
        float ov[4];
        #pragma unroll
        for (int c = 0; c < 4; c++) {
            int w = i*4 + c;
            ov[c] = fmaf(mv[c], 1.f - wwn*ev_s[w], wwn*wv_s[w]);
            nrm += ov[c]*ov[c];
            s0 = fmaf(ov[c], rk_s[w][0], s0);
            s1 = fmaf(ov[c], rk_s[w][1], s1);
            s2 = fmaf(ov[c], rk_s[w][2], s2);
            s3 = fmaf(ov[c], rk_s[w][3], s3);
        }
        float4 o4 = make_float4(ov[0], ov[1], ov[2], ov[3]);
        orow[i] = o4;
    }
    const float nn = sqrtf(nrm);
    float4 zr;
    zr.x = rs_s[0]*s0 / (nn*nrk_s[0] + EPSC);
    zr.y = rs_s[1]*s1 / (nn*nrk_s[1] + EPSC);
    zr.z = rs_s[2]*s2 / (nn*nrk_s[2] + EPSC);
    zr.w = rs_s[3]*s3 / (nn*nrk_s[3] + EPSC);
    *(float4*)(g_zr + bn*RR) = zr;
}

// ---------------- K5: softmax(cbr) per (b,r) ---------------------------------
__global__ void k5_cbr() {
    const int r = blockIdx.x, b = blockIdx.y;
    const int tid = threadIdx.x;  // 256
    __shared__ float sh[8];
    const size_t bo = (size_t)b*NN;

    float z[16];
    float lm = -3.4e38f;
    #pragma unroll
    for (int k = 0; k < 16; k++) {
        size_t idx = (bo + tid + (size_t)k*256)*RR + r;
        z[k] = g_zr[idx];
        lm = fmaxf(lm, z[k]);
    }
    for (int o = 16; o; o >>= 1) lm = fmaxf(lm, __shfl_xor_sync(0xffffffffu, lm, o));
    if ((tid & 31) == 0) sh[tid >> 5] = lm;
    __syncthreads();
    if (tid < 8) {
        float v = sh[tid];
        for (int o = 4; o; o >>= 1) v = fmaxf(v, __shfl_xor_sync(0xffu, v, o));
        if (tid == 0) sh[0] = v;
    }
    __syncthreads();
    const float bmax = sh[0];
    __syncthreads();

    float ls = 0.f;
    #pragma unroll
    for (int k = 0; k < 16; k++) { z[k] = expf(z[k] - bmax); ls += z[k]; }
    for (int o = 16; o; o >>= 1) ls += __shfl_xor_sync(0xffffffffu, ls, o);
    if ((tid & 31) == 0) sh[tid >> 5] = ls;
    __syncthreads();
    if (tid < 8) {
        float v = sh[tid];
        for (int o = 4; o; o >>= 1) v += __shfl_xor_sync(0xffu, v, o);
        if (tid == 0) sh[0] = v;
    }
    __syncthreads();
    const float bsum = sh[0];

    #pragma unroll
    for (int k = 0; k < 16; k++) {
        size_t idx = (bo + tid + (size_t)k*256)*RR + r;
        g_cbr[idx] = z[k] / bsum;
    }
}

// ---------------- K6 v6: f32x2-packed fused link update + fwd/bwd ------------
// a[n][m] = (1-ww_n-ww_m)*L[n][m] + ww_n*p_m  (diag corrected in K7)
// fwd[n,r] += a[n][m]*rwo[m,r]   ;   bwd[m,r] += a[n][m]*rwo[n,r]
// 2 cols/thread; rows packed in pairs into f32x2 (lo=even row, hi=odd row).
#define K6_TM  64     // cols per block (32 lanes x 2)
#define K6_CH  64     // rows per chunk (8 warps x 8)
#define K6_NCH 4      // chunks -> 256 rows per block
__global__ void __launch_bounds__(256, 2) k6_link(const float* __restrict__ L,
                        const float* __restrict__ rwo,
                        const float* __restrict__ prec) {
    const int b    = blockIdx.z;
    const int m0   = blockIdx.x * K6_TM;
    const int n00  = blockIdx.y * (K6_CH * K6_NCH);
    const int tid  = threadIdx.x;     // 256
    const int warp = tid >> 5, lane = tid & 31;
    const size_t bo = (size_t)b * NN;
    const int mc   = m0 + lane * 2;   // this thread's 2 columns

    __shared__ float wwn_s[K6_CH];
    __shared__ __align__(16) float4 rn_s[K6_CH];
    __shared__ __align__(16) float bw_s[8][K6_TM][4];   // per-warp bwd slabs

    // per-thread column constants (dup-packed)
    const float2 wmv = *(const float2*)(g_ww + bo + mc);
    const float2 pmv = *(const float2*)(prec + bo + mc);
    const u64 negwm_d[2] = { pack2(-wmv.x, -wmv.x), pack2(-wmv.y, -wmv.y) };
    const u64 pm_d[2]    = { pack2(pmv.x, pmv.x),   pack2(pmv.y, pmv.y) };
    const float4 rm0 = __ldg((const float4*)(rwo + (size_t)(bo + mc + 0)*4));
    const float4 rm1 = __ldg((const float4*)(rwo + (size_t)(bo + mc + 1)*4));
    u64 rm_d[2][4];
    rm_d[0][0] = pack2(rm0.x, rm0.x); rm_d[0][1] = pack2(rm0.y, rm0.y);
    rm_d[0][2] = pack2(rm0.z, rm0.z); rm_d[0][3] = pack2(rm0.w, rm0.w);
    rm_d[1][0] = pack2(rm1.x, rm1.x); rm_d[1][1] = pack2(rm1.y, rm1.y);
    rm_d[1][2] = pack2(rm1.z, rm1.z); rm_d[1][3] = pack2(rm1.w, rm1.w);

    u64 bacc_p[2][4];   // bwd partials [col][r]; lo=even-row sum, hi=odd-row sum
    #pragma unroll
    for (int c = 0; c < 2; c++)
        #pragma unroll
        for (int r = 0; r < 4; r++) bacc_p[c][r] = 0ull;

    for (int ch = 0; ch < K6_NCH; ch++) {
        const int n0 = n00 + ch * K6_CH;
        __syncthreads();
        if (tid < K6_CH) {
            wwn_s[tid] = g_ww[bo + n0 + tid];
            rn_s[tid]  = *(const float4*)(rwo + (size_t)(bo + n0 + tid)*4);
        }
        __syncthreads();

        #pragma unroll
        for (int g = 0; g < 2; g++) {
            const int rb = warp * 8 + g * 4;   // this group's 4 rows
            float2 lvf[4];
            const float* Lb = L + (bo + n0 + rb) * (size_t)NN + mc;
            #pragma unroll
            for (int k = 0; k < 4; k++)
                lvf[k] = __ldg((const float2*)(Lb + (size_t)k * NN));

            // row-pair packs (kp=0: rows rb+0,rb+1 ; kp=1: rows rb+2,rb+3)
            u64 v_p[8];   // [kp*4 + r] : (v[row_even][r], v[row_odd][r])
            #pragma unroll
            for (int i = 0; i < 8; i++) v_p[i] = 0ull;

            #pragma unroll
            for (int kp = 0; kp < 2; kp++) {
                const int k0 = 2*kp, k1 = 2*kp + 1;
                const float w0 = wwn_s[rb + k0], w1 = wwn_s[rb + k1];
                const u64 AA = pack2(1.f - w0, 1.f - w1);
                const u64 WWp = pack2(w0, w1);
                const float4 rnA = rn_s[rb + k0];
                const float4 rnB = rn_s[rb + k1];
                u64 rn_p[4];
                rn_p[0] = pack2(rnA.x, rnB.x); rn_p[1] = pack2(rnA.y, rnB.y);
                rn_p[2] = pack2(rnA.z, rnB.z); rn_p[3] = pack2(rnA.w, rnB.w);
                u64 lv_p[2];
                lv_p[0] = pack2(lvf[k0].x, lvf[k1].x);
                lv_p[1] = pack2(lvf[k0].y, lvf[k1].y);

                #pragma unroll
                for (int c = 0; c < 2; c++) {
                    const u64 aw = add2(AA, negwm_d[c]);
                    const u64 t  = mul2(WWp, pm_d[c]);
                    const u64 ap = fma2(lv_p[c], aw, t);
                    #pragma unroll
                    for (int r = 0; r < 4; r++) {
                        bacc_p[c][r]   = fma2(ap, rn_p[r],    bacc_p[c][r]);
                        v_p[kp*4 + r]  = fma2(ap, rm_d[c][r], v_p[kp*4 + r]);
                    }
                }
            }

            // packed reduce-scatter: 8 u64 items over 32 lanes
            // rounds h=16(half=4), h=8(half=2), h=4(half=1)
            {
                bool up;
                up = (lane & 16) != 0;
                #pragma unroll
                for (int i = 0; i < 4; i++) {
                    u64 send = up ? v_p[i] : v_p[i+4];
                    u64 recv = __shfl_xor_sync(0xffffffffu, send, 16);
                    v_p[i] = add2(up ? v_p[i+4] : v_p[i], recv);
                }
                up = (lane & 8) != 0;
                #pragma unroll
                for (int i = 0; i < 2; i++) {
                    u64 send = up ? v_p[i] : v_p[i+2];
                    u64 recv = __shfl_xor_sync(0xffffffffu, send, 8);
                    v_p[i] = add2(up ? v_p[i+2] : v_p[i], recv);
                }
                up = (lane & 4) != 0;
                {
                    u64 send = up ? v_p[0] : v_p[1];
                    u64 recv = __shfl_xor_sync(0xffffffffu, send, 4);
                    v_p[0] = add2(up ? v_p[1] : v_p[0], recv);
                }
                // full folds over remaining lane bits 1,0
                v_p[0] = add2(v_p[0], __shfl_xor_sync(0xffffffffu, v_p[0], 2));
                v_p[0] = add2(v_p[0], __shfl_xor_sync(0xffffffffu, v_p[0], 1));
            }
            // lane holds item j = 4*bit4 + 2*bit3 + bit2 ; j = kp*4 + r
            if ((lane & 3) == 0) {
                const int j  = ((lane >> 4) & 1) * 4 + ((lane >> 3) & 1) * 2 + ((lane >> 2) & 1);
                const int kp = j >> 2, r = j & 3;
                float lo, hi;
                unpack2(lo, hi, v_p[0]);
                const size_t rowb = bo + n0 + rb + 2*kp;
                atomicAdd(g_fwd + rowb*4 + r,       lo);
                atomicAdd(g_fwd + (rowb + 1)*4 + r, hi);
            }
        }
    }

    // bwd merge: unpack (even+odd halves), per-warp smem slabs, tree add + RED
    __syncthreads();
    {
        float b0[4], b1[4];
        #pragma unroll
        for (int r = 0; r < 4; r++) {
            float lo, hi;
            unpack2(lo, hi, bacc_p[0][r]); b0[r] = lo + hi;
            unpack2(lo, hi, bacc_p[1][r]); b1[r] = lo + hi;
        }
        *(float4*)&bw_s[warp][lane*2 + 0][0] = make_float4(b0[0], b0[1], b0[2], b0[3]);
        *(float4*)&bw_s[warp][lane*2 + 1][0] = make_float4(b1[0], b1[1], b1[2], b1[3]);
    }
    __syncthreads();
    {
        const int col = tid >> 2, r = tid & 3;   // 256 threads = 64 cols x 4 r
        float s = bw_s[0][col][r] + bw_s[1][col][r] + bw_s[2][col][r] + bw_s[3][col][r]
                + bw_s[4][col][r] + bw_s[5][col][r] + bw_s[6][col][r] + bw_s[7][col][r];
        atomicAdd(g_bwd + (size_t)(bo + m0 + col)*4 + r, s);
    }
}

// ---------------- K7: combine read modes (+ diag correction) + bwr -----------
__global__ void k7_read(const float* __restrict__ read_modes,
                        const float* __restrict__ L,
                        const float* __restrict__ prec,
                        const float* __restrict__ rwo,
                        float* __restrict__ out) {
    const int b   = blockIdx.y;
    const int n0  = blockIdx.x * 512;
    const int tid = threadIdx.x;          // 256
    const int w = tid & 63, r = tid >> 6;
    const size_t bo = (size_t)b * NN;
    __shared__ float rw_s[64][4];
    const int nl = tid >> 2, rr = tid & 3;
    const float mm0 = read_modes[b*12 + rr];
    const float mm1 = read_modes[b*12 + 4 + rr];
    const float mm2 = read_modes[b*12 + 8 + rr];

    float acc = 0.f;
    for (int c = 0; c < 512; c += 64) {
        const int n = n0 + c + nl;
        size_t idx = (bo + n)*4 + rr;
        // diag correction: a_nn = (1-2ww_n)L[n,n] + ww_n p_n ; subtract a_nn*rwo[n,r]
        const float Lnn = L[(bo + n)*(size_t)NN + n];
        const float wwn = g_ww[bo + n];
        const float ann = fmaf(1.f - 2.f*wwn, Lnn, wwn * prec[bo + n]);
        const float corr = ann * rwo[idx];
        float rwv = mm0*(g_bwd[idx] - corr) + mm1*g_cbr[idx] + mm2*(g_fwd[idx] - corr);
        __syncthreads();
        rw_s[nl][rr] = rwv;
        __syncthreads();
        const float* mp = g_memnew + (bo + n0 + c)*WW + w;
        #pragma unroll 8
        for (int q = 0; q < 64; q++)
            acc = fmaf(mp[(size_t)q*WW], rw_s[q][r], acc);
    }
    atomicAdd(&out[b*WW*RR + w*RR + r], acc);
}

// ---------------- launch -----------------------------------------------------
extern "C" void kernel_launch(void* const* d_in, const int* in_sizes, int n_in,
                              void* d_out, int out_size) {
    const float* erase_vector    = (const float*)d_in[0];
    const float* free_gates      = (const float*)d_in[1];
    const float* allocation_gate = (const float*)d_in[2];
    const float* write_gate      = (const float*)d_in[3];
    const float* read_modes      = (const float*)d_in[4];
    const float* read_strengths  = (const float*)d_in[5];
    const float* read_keys       = (const float*)d_in[6];
    const float* write_vector    = (const float*)d_in[7];
    const float* write_key       = (const float*)d_in[8];
    const float* write_strength  = (const float*)d_in[9];
    const float* memory          = (const float*)d_in[10];
    const float* read_weightings = (const float*)d_in[11];
    const float* write_weighting = (const float*)d_in[12];
    const float* memory_usage    = (const float*)d_in[13];
    const float* link_matrix     = (const float*)d_in[14];
    const float* precedence      = (const float*)d_in[15];
    float* out = (float*)d_out;

    k1_usage_sim<<<dim3(16, 8), 256>>>(memory, write_key, write_strength, free_gates,
                                       read_weightings, write_weighting, memory_usage, out);
    k2_alloc<<<8, 1024>>>();
    k3_ww<<<8, 1024>>>(allocation_gate, write_gate);
    // k6 at launch index 3 so ncu's fixed-skip capture lands on it
    k6_link<<<dim3(NN/K6_TM, NN/(K6_CH*K6_NCH), BB), 256>>>(link_matrix, read_weightings, precedence);
    k4_memupdate<<<dim3(16, 8), 256>>>(memory, erase_vector, write_vector,
                                       read_keys, read_strengths);
    k5_cbr<<<dim3(4, 8), 256>>>();
    k7_read<<<dim3(8, 8), 256>>>(read_modes, link_matrix, precedence, read_weightings, out);
}

// round 13
// speedup vs baseline: 1.2720x; 1.0834x over previous
#include <cuda_runtime.h>
#include <math.h>

#define BB 8
#define NN 4096
#define WW 64
#define RR 4
#define EPSC 1e-8f

typedef unsigned long long u64;

// ---- f32x2 packed helpers (sm_103a) -----------------------------------------
__device__ __forceinline__ u64 pack2(float lo, float hi) {
    u64 r; asm("mov.b64 %0, {%1, %2};" : "=l"(r) : "f"(lo), "f"(hi)); return r;
}
__device__ __forceinline__ void unpack2(float& lo, float& hi, u64 v) {
    asm("mov.b64 {%0, %1}, %2;" : "=f"(lo), "=f"(hi) : "l"(v));
}
__device__ __forceinline__ u64 fma2(u64 a, u64 b, u64 c) {
    u64 d; asm("fma.rn.f32x2 %0, %1, %2, %3;" : "=l"(d) : "l"(a), "l"(b), "l"(c)); return d;
}
__device__ __forceinline__ u64 add2(u64 a, u64 b) {
    u64 d; asm("add.rn.f32x2 %0, %1, %2;" : "=l"(d) : "l"(a), "l"(b)); return d;
}
__device__ __forceinline__ u64 mul2(u64 a, u64 b) {
    u64 d; asm("mul.rn.f32x2 %0, %1, %2;" : "=l"(d) : "l"(a), "l"(b)); return d;
}

// ---------------- scratch (no allocs allowed -> __device__ globals) ----------
__device__ __align__(16) float g_usage[BB*NN];
__device__ __align__(16) float g_zw[BB*NN];
__device__ __align__(16) float g_alloc[BB*NN];
__device__ __align__(16) float g_ww[BB*NN];
__device__ __align__(16) float g_memnew[BB*NN*WW];
__device__ __align__(16) float g_zr[BB*NN*RR];
__device__ __align__(16) float g_cbr[BB*NN*RR];
__device__ __align__(16) float g_fwd[BB*NN*RR];
__device__ __align__(16) float g_bwd[BB*NN*RR];

// ---------------- K1: new usage + write content scores; zero d_out -----------
__global__ void k1_usage_sim(const float* __restrict__ memory,
                             const float* __restrict__ write_key,
                             const float* __restrict__ write_strength,
                             const float* __restrict__ free_gates,
                             const float* __restrict__ read_weightings,
                             const float* __restrict__ write_weighting,
                             const float* __restrict__ memory_usage,
                             float* __restrict__ out) {
    const int b   = blockIdx.y;
    const int tid = threadIdx.x;
    const int n   = blockIdx.x * 256 + tid;
    __shared__ float wk_s[WW];
    __shared__ float fg_s[RR];
    __shared__ float wkn;
    if (tid < WW) wk_s[tid] = write_key[b*WW + tid];
    if (tid < RR) fg_s[tid] = free_gates[b*RR + tid];
    if (blockIdx.y == 0 && blockIdx.x < 8) out[blockIdx.x*256 + tid] = 0.0f;
    __syncthreads();
    if (tid == 0) {
        float s = 0.f;
        for (int w = 0; w < WW; w++) s += wk_s[w]*wk_s[w];
        wkn = sqrtf(s);
    }
    __syncthreads();

    const size_t bn = (size_t)b*NN + n;
    float u  = memory_usage[bn];
    float wv = write_weighting[bn];
    float uw = u + wv - u*wv;
    float4 rw = *(const float4*)(read_weightings + bn*RR);
    float prod = (1.f - rw.x*fg_s[0]) * (1.f - rw.y*fg_s[1])
               * (1.f - rw.z*fg_s[2]) * (1.f - rw.w*fg_s[3]);
    g_usage[bn] = uw * prod;

    const float4* mrow = (const float4*)(memory + bn*WW);
    float dot = 0.f, nrm = 0.f;
    #pragma unroll
    for (int i = 0; i < 16; i++) {
        float4 m = mrow[i];
        dot += m.x*wk_s[i*4+0] + m.y*wk_s[i*4+1] + m.z*wk_s[i*4+2] + m.w*wk_s[i*4+3];
        nrm += m.x*m.x + m.y*m.y + m.z*m.z + m.w*m.w;
    }
    float sim = dot / (wkn * sqrtf(nrm) + EPSC);
    g_zw[bn] = write_strength[b] * sim;
}

// ---------------- K2: per-batch sort -> allocation weights (1024 thr) --------
__global__ void k2_alloc() {
    const int b   = blockIdx.x;
    const int tid = threadIdx.x;  // 1024 threads
    __shared__ float sv[NN];
    __shared__ int   si[NN];
    __shared__ float cp[1024];

    for (int i = tid; i < NN; i += 1024) { sv[i] = g_usage[(size_t)b*NN + i]; si[i] = i; }
    __syncthreads();

    for (int k = 2; k <= NN; k <<= 1) {
        for (int j = k >> 1; j > 0; j >>= 1) {
            for (int i = tid; i < NN; i += 1024) {
                int ixj = i ^ j;
                if (ixj > i) {
                    bool up = ((i & k) == 0);
                    float a = sv[i], c = sv[ixj];
                    bool sw = up ? (a > c) : (a < c);
                    if (sw) {
                        sv[i] = c; sv[ixj] = a;
                        int t = si[i]; si[i] = si[ixj]; si[ixj] = t;
                    }
                }
            }
            __syncthreads();
        }
    }

    float p = 1.f;
    const int base = tid * 4;
    #pragma unroll
    for (int t = 0; t < 4; t++) p *= sv[base + t];
    cp[tid] = p;
    __syncthreads();
    for (int off = 1; off < 1024; off <<= 1) {
        float v = cp[tid];
        float o = (tid >= off) ? cp[tid - off] : 1.f;
        __syncthreads();
        cp[tid] = v * o;
        __syncthreads();
    }
    float run = (tid == 0) ? 1.f : cp[tid - 1];
    #pragma unroll
    for (int t = 0; t < 4; t++) {
        float v = sv[base + t];
        g_alloc[(size_t)b*NN + si[base + t]] = (1.f - v) * run;
        run *= v;
    }
}

// ---------------- K3: softmax(cbw) + final ww; also zero g_fwd/g_bwd ---------
__global__ void k3_ww(const float* __restrict__ allocation_gate,
                      const float* __restrict__ write_gate) {
    const int b   = blockIdx.x;
    const int tid = threadIdx.x;  // 1024
    __shared__ float sh[32];
    const size_t bo = (size_t)b*NN;

    {
        float4 z4 = make_float4(0.f, 0.f, 0.f, 0.f);
        float4* f4 = (float4*)(g_fwd + bo*RR);
        float4* b4 = (float4*)(g_bwd + bo*RR);
        #pragma unroll
        for (int i = 0; i < 4; i++) { f4[tid + i*1024] = z4; b4[tid + i*1024] = z4; }
    }

    float z[4];
    float lm = -3.4e38f;
    #pragma unroll
    for (int k = 0; k < 4; k++) { z[k] = g_zw[bo + tid + k*1024]; lm = fmaxf(lm, z[k]); }
    for (int o = 16; o; o >>= 1) lm = fmaxf(lm, __shfl_xor_sync(0xffffffffu, lm, o));
    if ((tid & 31) == 0) sh[tid >> 5] = lm;
    __syncthreads();
    if (tid < 32) {
        float v = sh[tid];
        for (int o = 16; o; o >>= 1) v = fmaxf(v, __shfl_xor_sync(0xffffffffu, v, o));
        if (tid == 0) sh[0] = v;
    }
    __syncthreads();
    const float bmax = sh[0];
    __syncthreads();

    float e[4], ls = 0.f;
    #pragma unroll
    for (int k = 0; k < 4; k++) { e[k] = expf(z[k] - bmax); ls += e[k]; }
    for (int o = 16; o; o >>= 1) ls += __shfl_xor_sync(0xffffffffu, ls, o);
    if ((tid & 31) == 0) sh[tid >> 5] = ls;
    __syncthreads();
    if (tid < 32) {
        float v = sh[tid];
        for (int o = 16; o; o >>= 1) v += __shfl_xor_sync(0xffffffffu, v, o);
        if (tid == 0) sh[0] = v;
    }
    __syncthreads();
    const float bsum = sh[0];

    const float ag = allocation_gate[b], wg = write_gate[b];
    #pragma unroll
    for (int k = 0; k < 4; k++) {
        size_t idx = bo + tid + k*1024;
        float cbw = e[k] / bsum;
        g_ww[idx] = wg * (ag * g_alloc[idx] + (1.f - ag) * cbw);
    }
}

// ---------------- K4: memory erase/write + read content scores --------------
__global__ void k4_memupdate(const float* __restrict__ memory,
                             const float* __restrict__ erase_vector,
                             const float* __restrict__ write_vector,
                             const float* __restrict__ read_keys,
                             const float* __restrict__ read_strengths) {
    const int b   = blockIdx.y;
    const int tid = threadIdx.x;
    const int n   = blockIdx.x * 256 + tid;
    __shared__ float rk_s[WW][RR];
    __shared__ float ev_s[WW], wv_s[WW];
    __shared__ float nrk_s[RR], rs_s[RR];

    if (tid < WW) { ev_s[tid] = erase_vector[b*WW + tid]; wv_s[tid] = write_vector[b*WW + tid]; }
    { int w = tid >> 2, r = tid & 3; rk_s[w][r] = read_keys[b*WW*RR + tid]; }
    __syncthreads();
    if (tid < RR) {
        float s = 0.f;
        for (int w = 0; w < WW; w++) { float v = rk_s[w][tid]; s += v*v; }
        nrk_s[tid] = sqrtf(s);
        rs_s[tid]  = read_strengths[b*RR + tid];
    }
    __syncthreads();

    const size_t bn = (size_t)b*NN + n;
    const float wwn = g_ww[bn];
    const float4* mrow = (const float4*)(memory + bn*WW);
    float4* orow = (float4*)(g_memnew + bn*WW);

    float nrm = 0.f, s0 = 0.f, s1 = 0.f, s2 = 0.f, s3 = 0.f;
    #pragma unroll
    for (int i = 0; i < 16; i++) {
        float4 m = mrow[i];
        float mv[4] = {m.x, m.y, m.z, m.w};
        float ov[4];
        #pragma unroll
        for (int c = 0; c < 4; c++) {
            int w = i*4 + c;
            ov[c] = fmaf(mv[c], 1.f - wwn*ev_s[w], wwn*wv_s[w]);
            nrm += ov[c]*ov[c];
            s0 = fmaf(ov[c], rk_s[w][0], s0);
            s1 = fmaf(ov[c], rk_s[w][1], s1);
            s2 = fmaf(ov[c], rk_s[w][2], s2);
            s3 = fmaf(ov[c], rk_s[w][3], s3);
        }
        float4 o4 = make_float4(ov[0], ov[1], ov[2], ov[3]);
        orow[i] = o4;
    }
    const float nn = sqrtf(nrm);
    float4 zr;
    zr.x = rs_s[0]*s0 / (nn*nrk_s[0] + EPSC);
    zr.y = rs_s[1]*s1 / (nn*nrk_s[1] + EPSC);
    zr.z = rs_s[2]*s2 / (nn*nrk_s[2] + EPSC);
    zr.w = rs_s[3]*s3 / (nn*nrk_s[3] + EPSC);
    *(float4*)(g_zr + bn*RR) = zr;
}

// ---------------- K5: softmax(cbr) per (b,r) ---------------------------------
__global__ void k5_cbr() {
    const int r = blockIdx.x, b = blockIdx.y;
    const int tid = threadIdx.x;  // 256
    __shared__ float sh[8];
    const size_t bo = (size_t)b*NN;

    float z[16];
    float lm = -3.4e38f;
    #pragma unroll
    for (int k = 0; k < 16; k++) {
        size_t idx = (bo + tid + (size_t)k*256)*RR + r;
        z[k] = g_zr[idx];
        lm = fmaxf(lm, z[k]);
    }
    for (int o = 16; o; o >>= 1) lm = fmaxf(lm, __shfl_xor_sync(0xffffffffu, lm, o));
    if ((tid & 31) == 0) sh[tid >> 5] = lm;
    __syncthreads();
    if (tid < 8) {
        float v = sh[tid];
        for (int o = 4; o; o >>= 1) v = fmaxf(v, __shfl_xor_sync(0xffu, v, o));
        if (tid == 0) sh[0] = v;
    }
    __syncthreads();
    const float bmax = sh[0];
    __syncthreads();

    float ls = 0.f;
    #pragma unroll
    for (int k = 0; k < 16; k++) { z[k] = expf(z[k] - bmax); ls += z[k]; }
    for (int o = 16; o; o >>= 1) ls += __shfl_xor_sync(0xffffffffu, ls, o);
    if ((tid & 31) == 0) sh[tid >> 5] = ls;
    __syncthreads();
    if (tid < 8) {
        float v = sh[tid];
        for (int o = 4; o; o >>= 1) v += __shfl_xor_sync(0xffu, v, o);
        if (tid == 0) sh[0] = v;
    }
    __syncthreads();
    const float bsum = sh[0];

    #pragma unroll
    for (int k = 0; k < 16; k++) {
        size_t idx = (bo + tid + (size_t)k*256)*RR + r;
        g_cbr[idx] = z[k] / bsum;
    }
}

// ---------------- K6 v7: f32x2-packed, 2-row groups, 3 blocks/SM -------------
// a[n][m] = (1-ww_n-ww_m)*L[n][m] + ww_n*p_m  (diag corrected in K7)
// fwd[n,r] += a[n][m]*rwo[m,r]   ;   bwd[m,r] += a[n][m]*rwo[n,r]
// 2 cols/thread; row pairs packed into f32x2 (lo=even row, hi=odd row).
#define K6_TM  64     // cols per block (32 lanes x 2)
#define K6_CH  64     // rows per chunk (8 warps x 8)
#define K6_NCH 4      // chunks -> 256 rows per block
__global__ void __launch_bounds__(256, 3) k6_link(const float* __restrict__ L,
                        const float* __restrict__ rwo,
                        const float* __restrict__ prec) {
    const int b    = blockIdx.z;
    const int m0   = blockIdx.x * K6_TM;
    const int n00  = blockIdx.y * (K6_CH * K6_NCH);
    const int tid  = threadIdx.x;     // 256
    const int warp = tid >> 5, lane = tid & 31;
    const size_t bo = (size_t)b * NN;
    const int mc   = m0 + lane * 2;   // this thread's 2 columns

    __shared__ float wwn_s[K6_CH];
    __shared__ __align__(16) float4 rn_s[K6_CH];
    __shared__ __align__(16) float bw_s[8][K6_TM][4];   // per-warp bwd slabs

    // per-thread column constants (dup-packed)
    const float2 wmv = *(const float2*)(g_ww + bo + mc);
    const float2 pmv = *(const float2*)(prec + bo + mc);
    const u64 negwm_d[2] = { pack2(-wmv.x, -wmv.x), pack2(-wmv.y, -wmv.y) };
    const u64 pm_d[2]    = { pack2(pmv.x, pmv.x),   pack2(pmv.y, pmv.y) };
    const float4 rm0 = __ldg((const float4*)(rwo + (size_t)(bo + mc + 0)*4));
    const float4 rm1 = __ldg((const float4*)(rwo + (size_t)(bo + mc + 1)*4));
    u64 rm_d[2][4];
    rm_d[0][0] = pack2(rm0.x, rm0.x); rm_d[0][1] = pack2(rm0.y, rm0.y);
    rm_d[0][2] = pack2(rm0.z, rm0.z); rm_d[0][3] = pack2(rm0.w, rm0.w);
    rm_d[1][0] = pack2(rm1.x, rm1.x); rm_d[1][1] = pack2(rm1.y, rm1.y);
    rm_d[1][2] = pack2(rm1.z, rm1.z); rm_d[1][3] = pack2(rm1.w, rm1.w);

    u64 bacc_p[2][4];   // bwd partials [col][r]; lo=even-row sum, hi=odd-row sum
    #pragma unroll
    for (int c = 0; c < 2; c++)
        #pragma unroll
        for (int r = 0; r < 4; r++) bacc_p[c][r] = 0ull;

    for (int ch = 0; ch < K6_NCH; ch++) {
        const int n0 = n00 + ch * K6_CH;
        __syncthreads();
        if (tid < K6_CH) {
            wwn_s[tid] = g_ww[bo + n0 + tid];
            rn_s[tid]  = *(const float4*)(rwo + (size_t)(bo + n0 + tid)*4);
        }
        __syncthreads();

        #pragma unroll
        for (int g = 0; g < 4; g++) {
            const int rb = warp * 8 + g * 2;   // this group's 2 rows
            float2 lvf[2];
            const float* Lb = L + (bo + n0 + rb) * (size_t)NN + mc;
            lvf[0] = __ldg((const float2*)(Lb));
            lvf[1] = __ldg((const float2*)(Lb + (size_t)NN));

            const float w0 = wwn_s[rb + 0], w1 = wwn_s[rb + 1];
            const u64 AA  = pack2(1.f - w0, 1.f - w1);
            const u64 WWp = pack2(w0, w1);
            const float4 rnA = rn_s[rb + 0];
            const float4 rnB = rn_s[rb + 1];
            u64 rn_p[4];
            rn_p[0] = pack2(rnA.x, rnB.x); rn_p[1] = pack2(rnA.y, rnB.y);
            rn_p[2] = pack2(rnA.z, rnB.z); rn_p[3] = pack2(rnA.w, rnB.w);
            u64 lv_p[2];
            lv_p[0] = pack2(lvf[0].x, lvf[1].x);
            lv_p[1] = pack2(lvf[0].y, lvf[1].y);

            u64 v_p[4];   // fwd partials per r: (row_even, row_odd)
            {
                const u64 aw0 = add2(AA, negwm_d[0]);
                const u64 t0  = mul2(WWp, pm_d[0]);
                const u64 ap0 = fma2(lv_p[0], aw0, t0);
                #pragma unroll
                for (int r = 0; r < 4; r++) {
                    bacc_p[0][r] = fma2(ap0, rn_p[r], bacc_p[0][r]);
                    v_p[r] = mul2(ap0, rm_d[0][r]);
                }
                const u64 aw1 = add2(AA, negwm_d[1]);
                const u64 t1  = mul2(WWp, pm_d[1]);
                const u64 ap1 = fma2(lv_p[1], aw1, t1);
                #pragma unroll
                for (int r = 0; r < 4; r++) {
                    bacc_p[1][r] = fma2(ap1, rn_p[r], bacc_p[1][r]);
                    v_p[r] = fma2(ap1, rm_d[1][r], v_p[r]);
                }
            }

            // packed reduce-scatter: 4 u64 items over 32 lanes
            {
                bool up;
                up = (lane & 16) != 0;
                #pragma unroll
                for (int i = 0; i < 2; i++) {
                    u64 send = up ? v_p[i] : v_p[i+2];
                    u64 recv = __shfl_xor_sync(0xffffffffu, send, 16);
                    v_p[i] = add2(up ? v_p[i+2] : v_p[i], recv);
                }
                up = (lane & 8) != 0;
                {
                    u64 send = up ? v_p[0] : v_p[1];
                    u64 recv = __shfl_xor_sync(0xffffffffu, send, 8);
                    v_p[0] = add2(up ? v_p[1] : v_p[0], recv);
                }
                v_p[0] = add2(v_p[0], __shfl_xor_sync(0xffffffffu, v_p[0], 4));
                v_p[0] = add2(v_p[0], __shfl_xor_sync(0xffffffffu, v_p[0], 2));
                v_p[0] = add2(v_p[0], __shfl_xor_sync(0xffffffffu, v_p[0], 1));
            }
            // lane holds item j = 2*bit4 + bit3 = r ; writers: lane%8 == 0
            if ((lane & 7) == 0) {
                const int r = (((lane >> 4) & 1) << 1) | ((lane >> 3) & 1);
                float lo, hi;
                unpack2(lo, hi, v_p[0]);
                const size_t rowb = bo + n0 + rb;
                atomicAdd(g_fwd + rowb*4 + r,       lo);
                atomicAdd(g_fwd + (rowb + 1)*4 + r, hi);
            }
        }
    }

    // bwd merge: unpack (even+odd halves), per-warp smem slabs, tree add + RED
    __syncthreads();
    {
        float b0[4], b1[4];
        #pragma unroll
        for (int r = 0; r < 4; r++) {
            float lo, hi;
            unpack2(lo, hi, bacc_p[0][r]); b0[r] = lo + hi;
            unpack2(lo, hi, bacc_p[1][r]); b1[r] = lo + hi;
        }
        *(float4*)&bw_s[warp][lane*2 + 0][0] = make_float4(b0[0], b0[1], b0[2], b0[3]);
        *(float4*)&bw_s[warp][lane*2 + 1][0] = make_float4(b1[0], b1[1], b1[2], b1[3]);
    }
    __syncthreads();
    {
        const int col = tid >> 2, r = tid & 3;   // 256 threads = 64 cols x 4 r
        float s = bw_s[0][col][r] + bw_s[1][col][r] + bw_s[2][col][r] + bw_s[3][col][r]
                + bw_s[4][col][r] + bw_s[5][col][r] + bw_s[6][col][r] + bw_s[7][col][r];
        atomicAdd(g_bwd + (size_t)(bo + m0 + col)*4 + r, s);
    }
}

// ---------------- K7: combine read modes (+ diag correction) + bwr -----------
__global__ void k7_read(const float* __restrict__ read_modes,
                        const float* __restrict__ L,
                        const float* __restrict__ prec,
                        const float* __restrict__ rwo,
                        float* __restrict__ out) {
    const int b   = blockIdx.y;
    const int n0  = blockIdx.x * 512;
    const int tid = threadIdx.x;          // 256
    const int w = tid & 63, r = tid >> 6;
    const size_t bo = (size_t)b * NN;
    __shared__ float rw_s[64][4];
    const int nl = tid >> 2, rr = tid & 3;
    const float mm0 = read_modes[b*12 + rr];
    const float mm1 = read_modes[b*12 + 4 + rr];
    const float mm2 = read_modes[b*12 + 8 + rr];

    float acc = 0.f;
    for (int c = 0; c < 512; c += 64) {
        const int n = n0 + c + nl;
        size_t idx = (bo + n)*4 + rr;
        // diag correction: a_nn = (1-2ww_n)L[n,n] + ww_n p_n ; subtract a_nn*rwo[n,r]
        const float Lnn = L[(bo + n)*(size_t)NN + n];
        const float wwn = g_ww[bo + n];
        const float ann = fmaf(1.f - 2.f*wwn, Lnn, wwn * prec[bo + n]);
        const float corr = ann * rwo[idx];
        float rwv = mm0*(g_bwd[idx] - corr) + mm1*g_cbr[idx] + mm2*(g_fwd[idx] - corr);
        __syncthreads();
        rw_s[nl][rr] = rwv;
        __syncthreads();
        const float* mp = g_memnew + (bo + n0 + c)*WW + w;
        #pragma unroll 8
        for (int q = 0; q < 64; q++)
            acc = fmaf(mp[(size_t)q*WW], rw_s[q][r], acc);
    }
    atomicAdd(&out[b*WW*RR + w*RR + r], acc);
}

// ---------------- launch -----------------------------------------------------
extern "C" void kernel_launch(void* const* d_in, const int* in_sizes, int n_in,
                              void* d_out, int out_size) {
    const float* erase_vector    = (const float*)d_in[0];
    const float* free_gates      = (const float*)d_in[1];
    const float* allocation_gate = (const float*)d_in[2];
    const float* write_gate      = (const float*)d_in[3];
    const float* read_modes      = (const float*)d_in[4];
    const float* read_strengths  = (const float*)d_in[5];
    const float* read_keys       = (const float*)d_in[6];
    const float* write_vector    = (const float*)d_in[7];
    const float* write_key       = (const float*)d_in[8];
    const float* write_strength  = (const float*)d_in[9];
    const float* memory          = (const float*)d_in[10];
    const float* read_weightings = (const float*)d_in[11];
    const float* write_weighting = (const float*)d_in[12];
    const float* memory_usage    = (const float*)d_in[13];
    const float* link_matrix     = (const float*)d_in[14];
    const float* precedence      = (const float*)d_in[15];
    float* out = (float*)d_out;

    k1_usage_sim<<<dim3(16, 8), 256>>>(memory, write_key, write_strength, free_gates,
                                       read_weightings, write_weighting, memory_usage, out);
    k2_alloc<<<8, 1024>>>();
    k3_ww<<<8, 1024>>>(allocation_gate, write_gate);
    // k6 at launch index 3 so ncu's fixed-skip capture lands on it
    k6_link<<<dim3(NN/K6_TM, NN/(K6_CH*K6_NCH), BB), 256>>>(link_matrix, read_weightings, precedence);
    k4_memupdate<<<dim3(16, 8), 256>>>(memory, erase_vector, write_vector,
                                       read_keys, read_strengths);
    k5_cbr<<<dim3(4, 8), 256>>>();
    k7_read<<<dim3(8, 8), 256>>>(read_modes, link_matrix, precedence, read_weightings, out);
}

// round 14
// speedup vs baseline: 1.4172x; 1.1142x over previous
#include <cuda_runtime.h>
#include <math.h>

#define BB 8
#define NN 4096
#define WW 64
#define RR 4
#define EPSC 1e-8f

typedef unsigned long long u64;

// ---- f32x2 packed helpers (sm_103a) -----------------------------------------
__device__ __forceinline__ u64 pack2(float lo, float hi) {
    u64 r; asm("mov.b64 %0, {%1, %2};" : "=l"(r) : "f"(lo), "f"(hi)); return r;
}
__device__ __forceinline__ void unpack2(float& lo, float& hi, u64 v) {
    asm("mov.b64 {%0, %1}, %2;" : "=f"(lo), "=f"(hi) : "l"(v));
}
__device__ __forceinline__ u64 fma2(u64 a, u64 b, u64 c) {
    u64 d; asm("fma.rn.f32x2 %0, %1, %2, %3;" : "=l"(d) : "l"(a), "l"(b), "l"(c)); return d;
}
__device__ __forceinline__ u64 add2(u64 a, u64 b) {
    u64 d; asm("add.rn.f32x2 %0, %1, %2;" : "=l"(d) : "l"(a), "l"(b)); return d;
}
__device__ __forceinline__ u64 mul2(u64 a, u64 b) {
    u64 d; asm("mul.rn.f32x2 %0, %1, %2;" : "=l"(d) : "l"(a), "l"(b)); return d;
}

// ---------------- scratch (no allocs allowed -> __device__ globals) ----------
__device__ __align__(16) float g_usage[BB*NN];
__device__ __align__(16) float g_zw[BB*NN];
__device__ __align__(16) float g_alloc[BB*NN];
__device__ __align__(16) float g_ww[BB*NN];
__device__ __align__(16) float g_memnew[BB*NN*WW];
__device__ __align__(16) float g_zr[BB*NN*RR];
__device__ __align__(16) float g_cbr[BB*NN*RR];
__device__ __align__(16) float g_fwd[BB*NN*RR];
__device__ __align__(16) float g_bwd[BB*NN*RR];

// ---------------- K1: new usage + write content scores; zero d_out -----------
__global__ void k1_usage_sim(const float* __restrict__ memory,
                             const float* __restrict__ write_key,
                             const float* __restrict__ write_strength,
                             const float* __restrict__ free_gates,
                             const float* __restrict__ read_weightings,
                             const float* __restrict__ write_weighting,
                             const float* __restrict__ memory_usage,
                             float* __restrict__ out) {
    const int b   = blockIdx.y;
    const int tid = threadIdx.x;
    const int n   = blockIdx.x * 256 + tid;
    __shared__ float wk_s[WW];
    __shared__ float fg_s[RR];
    __shared__ float wkn;
    if (tid < WW) wk_s[tid] = write_key[b*WW + tid];
    if (tid < RR) fg_s[tid] = free_gates[b*RR + tid];
    if (blockIdx.y == 0 && blockIdx.x < 8) out[blockIdx.x*256 + tid] = 0.0f;
    __syncthreads();
    if (tid == 0) {
        float s = 0.f;
        for (int w = 0; w < WW; w++) s += wk_s[w]*wk_s[w];
        wkn = sqrtf(s);
    }
    __syncthreads();

    const size_t bn = (size_t)b*NN + n;
    float u  = memory_usage[bn];
    float wv = write_weighting[bn];
    float uw = u + wv - u*wv;
    float4 rw = *(const float4*)(read_weightings + bn*RR);
    float prod = (1.f - rw.x*fg_s[0]) * (1.f - rw.y*fg_s[1])
               * (1.f - rw.z*fg_s[2]) * (1.f - rw.w*fg_s[3]);
    g_usage[bn] = uw * prod;

    const float4* mrow = (const float4*)(memory + bn*WW);
    float dot = 0.f, nrm = 0.f;
    #pragma unroll
    for (int i = 0; i < 16; i++) {
        float4 m = mrow[i];
        dot += m.x*wk_s[i*4+0] + m.y*wk_s[i*4+1] + m.z*wk_s[i*4+2] + m.w*wk_s[i*4+3];
        nrm += m.x*m.x + m.y*m.y + m.z*m.z + m.w*m.w;
    }
    float sim = dot / (wkn * sqrtf(nrm) + EPSC);
    g_zw[bn] = write_strength[b] * sim;
}

// ---------------- K2: per-batch sort -> allocation weights (1024 thr) --------
__global__ void k2_alloc() {
    const int b   = blockIdx.x;
    const int tid = threadIdx.x;  // 1024 threads
    __shared__ float sv[NN];
    __shared__ int   si[NN];
    __shared__ float cp[1024];

    for (int i = tid; i < NN; i += 1024) { sv[i] = g_usage[(size_t)b*NN + i]; si[i] = i; }
    __syncthreads();

    for (int k = 2; k <= NN; k <<= 1) {
        for (int j = k >> 1; j > 0; j >>= 1) {
            for (int i = tid; i < NN; i += 1024) {
                int ixj = i ^ j;
                if (ixj > i) {
                    bool up = ((i & k) == 0);
                    float a = sv[i], c = sv[ixj];
                    bool sw = up ? (a > c) : (a < c);
                    if (sw) {
                        sv[i] = c; sv[ixj] = a;
                        int t = si[i]; si[i] = si[ixj]; si[ixj] = t;
                    }
                }
            }
            __syncthreads();
        }
    }

    float p = 1.f;
    const int base = tid * 4;
    #pragma unroll
    for (int t = 0; t < 4; t++) p *= sv[base + t];
    cp[tid] = p;
    __syncthreads();
    for (int off = 1; off < 1024; off <<= 1) {
        float v = cp[tid];
        float o = (tid >= off) ? cp[tid - off] : 1.f;
        __syncthreads();
        cp[tid] = v * o;
        __syncthreads();
    }
    float run = (tid == 0) ? 1.f : cp[tid - 1];
    #pragma unroll
    for (int t = 0; t < 4; t++) {
        float v = sv[base + t];
        g_alloc[(size_t)b*NN + si[base + t]] = (1.f - v) * run;
        run *= v;
    }
}

// ---------------- K3: softmax(cbw) + final ww; also zero g_fwd/g_bwd ---------
__global__ void k3_ww(const float* __restrict__ allocation_gate,
                      const float* __restrict__ write_gate) {
    const int b   = blockIdx.x;
    const int tid = threadIdx.x;  // 1024
    __shared__ float sh[32];
    const size_t bo = (size_t)b*NN;

    {
        float4 z4 = make_float4(0.f, 0.f, 0.f, 0.f);
        float4* f4 = (float4*)(g_fwd + bo*RR);
        float4* b4 = (float4*)(g_bwd + bo*RR);
        #pragma unroll
        for (int i = 0; i < 4; i++) { f4[tid + i*1024] = z4; b4[tid + i*1024] = z4; }
    }

    float z[4];
    float lm = -3.4e38f;
    #pragma unroll
    for (int k = 0; k < 4; k++) { z[k] = g_zw[bo + tid + k*1024]; lm = fmaxf(lm, z[k]); }
    for (int o = 16; o; o >>= 1) lm = fmaxf(lm, __shfl_xor_sync(0xffffffffu, lm, o));
    if ((tid & 31) == 0) sh[tid >> 5] = lm;
    __syncthreads();
    if (tid < 32) {
        float v = sh[tid];
        for (int o = 16; o; o >>= 1) v = fmaxf(v, __shfl_xor_sync(0xffffffffu, v, o));
        if (tid == 0) sh[0] = v;
    }
    __syncthreads();
    const float bmax = sh[0];
    __syncthreads();

    float e[4], ls = 0.f;
    #pragma unroll
    for (int k = 0; k < 4; k++) { e[k] = expf(z[k] - bmax); ls += e[k]; }
    for (int o = 16; o; o >>= 1) ls += __shfl_xor_sync(0xffffffffu, ls, o);
    if ((tid & 31) == 0) sh[tid >> 5] = ls;
    __syncthreads();
    if (tid < 32) {
        float v = sh[tid];
        for (int o = 16; o; o >>= 1) v += __shfl_xor_sync(0xffffffffu, v, o);
        if (tid == 0) sh[0] = v;
    }
    __syncthreads();
    const float bsum = sh[0];

    const float ag = allocation_gate[b], wg = write_gate[b];
    #pragma unroll
    for (int k = 0; k < 4; k++) {
        size_t idx = bo + tid + k*1024;
        float cbw = e[k] / bsum;
        g_ww[idx] = wg * (ag * g_alloc[idx] + (1.f - ag) * cbw);
    }
}

// ---------------- K4: memory erase/write + read content scores --------------
__global__ void k4_memupdate(const float* __restrict__ memory,
                             const float* __restrict__ erase_vector,
                             const float* __restrict__ write_vector,
                             const float* __restrict__ read_keys,
                             const float* __restrict__ read_strengths) {
    const int b   = blockIdx.y;
    const int tid = threadIdx.x;
    const int n   = blockIdx.x * 256 + tid;
    __shared__ float rk_s[WW][RR];
    __shared__ float ev_s[WW], wv_s[WW];
    __shared__ float nrk_s[RR], rs_s[RR];

    if (tid < WW) { ev_s[tid] = erase_vector[b*WW + tid]; wv_s[tid] = write_vector[b*WW + tid]; }
    { int w = tid >> 2, r = tid & 3; rk_s[w][r] = read_keys[b*WW*RR + tid]; }
    __syncthreads();
    if (tid < RR) {
        float s = 0.f;
        for (int w = 0; w < WW; w++) { float v = rk_s[w][tid]; s += v*v; }
        nrk_s[tid] = sqrtf(s);
        rs_s[tid]  = read_strengths[b*RR + tid];
    }
    __syncthreads();

    const size_t bn = (size_t)b*NN + n;
    const float wwn = g_ww[bn];
    const float4* mrow = (const float4*)(memory + bn*WW);
    float4* orow = (float4*)(g_memnew + bn*WW);

    float nrm = 0.f, s0 = 0.f, s1 = 0.f, s2 = 0.f, s3 = 0.f;
    #pragma unroll
    for (int i = 0; i < 16; i++) {
        float4 m = mrow[i];
        float mv[4] = {m.x, m.y, m.z, m.w};
        float ov[4];
        #pragma unroll
        for (int c = 0; c < 4; c++) {
            int w = i*4 + c;
            ov[c] = fmaf(mv[c], 1.f - wwn*ev_s[w], wwn*wv_s[w]);
            nrm += ov[c]*ov[c];
            s0 = fmaf(ov[c], rk_s[w][0], s0);
            s1 = fmaf(ov[c], rk_s[w][1], s1);
            s2 = fmaf(ov[c], rk_s[w][2], s2);
            s3 = fmaf(ov[c], rk_s[w][3], s3);
        }
        float4 o4 = make_float4(ov[0], ov[1], ov[2], ov[3]);
        orow[i] = o4;
    }
    const float nn = sqrtf(nrm);
    float4 zr;
    zr.x = rs_s[0]*s0 / (nn*nrk_s[0] + EPSC);
    zr.y = rs_s[1]*s1 / (nn*nrk_s[1] + EPSC);
    zr.z = rs_s[2]*s2 / (nn*nrk_s[2] + EPSC);
    zr.w = rs_s[3]*s3 / (nn*nrk_s[3] + EPSC);
    *(float4*)(g_zr + bn*RR) = zr;
}

// ---------------- K5: softmax(cbr) per (b,r) ---------------------------------
__global__ void k5_cbr() {
    const int r = blockIdx.x, b = blockIdx.y;
    const int tid = threadIdx.x;  // 256
    __shared__ float sh[8];
    const size_t bo = (size_t)b*NN;

    float z[16];
    float lm = -3.4e38f;
    #pragma unroll
    for (int k = 0; k < 16; k++) {
        size_t idx = (bo + tid + (size_t)k*256)*RR + r;
        z[k] = g_zr[idx];
        lm = fmaxf(lm, z[k]);
    }
    for (int o = 16; o; o >>= 1) lm = fmaxf(lm, __shfl_xor_sync(0xffffffffu, lm, o));
    if ((tid & 31) == 0) sh[tid >> 5] = lm;
    __syncthreads();
    if (tid < 8) {
        float v = sh[tid];
        for (int o = 4; o; o >>= 1) v = fmaxf(v, __shfl_xor_sync(0xffu, v, o));
        if (tid == 0) sh[0] = v;
    }
    __syncthreads();
    const float bmax = sh[0];
    __syncthreads();

    float ls = 0.f;
    #pragma unroll
    for (int k = 0; k < 16; k++) { z[k] = expf(z[k] - bmax); ls += z[k]; }
    for (int o = 16; o; o >>= 1) ls += __shfl_xor_sync(0xffffffffu, ls, o);
    if ((tid & 31) == 0) sh[tid >> 5] = ls;
    __syncthreads();
    if (tid < 8) {
        float v = sh[tid];
        for (int o = 4; o; o >>= 1) v += __shfl_xor_sync(0xffu, v, o);
        if (tid == 0) sh[0] = v;
    }
    __syncthreads();
    const float bsum = sh[0];

    #pragma unroll
    for (int k = 0; k < 16; k++) {
        size_t idx = (bo + tid + (size_t)k*256)*RR + r;
        g_cbr[idx] = z[k] / bsum;
    }
}

// ---------------- K6 v8: single-stage smem, prefetch-1 pipeline --------------
// a[n][m] = (1-ww_n-ww_m)*L[n][m] + ww_n*p_m  (diag corrected in K7)
// fwd[n,r] += a[n][m]*rwo[m,r]   ;   bwd[m,r] += a[n][m]*rwo[n,r]
// 2 cols/thread; row pairs packed into f32x2 (lo=even row, hi=odd row).
#define K6_TM   64    // cols per block (32 lanes x 2)
#define K6_ROWS 256   // rows per block (8 warps x 16 groups of 2)
__global__ void __launch_bounds__(256, 3) k6_link(const float* __restrict__ L,
                        const float* __restrict__ rwo,
                        const float* __restrict__ prec) {
    const int b    = blockIdx.z;
    const int m0   = blockIdx.x * K6_TM;
    const int n00  = blockIdx.y * K6_ROWS;
    const int tid  = threadIdx.x;     // 256
    const int warp = tid >> 5, lane = tid & 31;
    const size_t bo = (size_t)b * NN;
    const int mc   = m0 + lane * 2;   // this thread's 2 columns

    __shared__ float wwn_s[K6_ROWS];
    __shared__ __align__(16) float4 rn_s[K6_ROWS];
    __shared__ __align__(16) float bw_s[8][K6_TM][4];   // per-warp bwd slabs

    // stage ALL rows once (one barrier for the whole mainloop)
    wwn_s[tid] = g_ww[bo + n00 + tid];
    rn_s[tid]  = *(const float4*)(rwo + (size_t)(bo + n00 + tid)*4);

    // per-thread column constants (dup-packed)
    const float2 wmv = *(const float2*)(g_ww + bo + mc);
    const float2 pmv = *(const float2*)(prec + bo + mc);
    const u64 negwm_d[2] = { pack2(-wmv.x, -wmv.x), pack2(-wmv.y, -wmv.y) };
    const u64 pm_d[2]    = { pack2(pmv.x, pmv.x),   pack2(pmv.y, pmv.y) };
    const float4 rm0 = __ldg((const float4*)(rwo + (size_t)(bo + mc + 0)*4));
    const float4 rm1 = __ldg((const float4*)(rwo + (size_t)(bo + mc + 1)*4));
    u64 rm_d[2][4];
    rm_d[0][0] = pack2(rm0.x, rm0.x); rm_d[0][1] = pack2(rm0.y, rm0.y);
    rm_d[0][2] = pack2(rm0.z, rm0.z); rm_d[0][3] = pack2(rm0.w, rm0.w);
    rm_d[1][0] = pack2(rm1.x, rm1.x); rm_d[1][1] = pack2(rm1.y, rm1.y);
    rm_d[1][2] = pack2(rm1.z, rm1.z); rm_d[1][3] = pack2(rm1.w, rm1.w);

    u64 bacc_p[2][4];   // bwd partials [col][r]; lo=even-row sum, hi=odd-row sum
    #pragma unroll
    for (int c = 0; c < 2; c++)
        #pragma unroll
        for (int r = 0; r < 4; r++) bacc_p[c][r] = 0ull;

    __syncthreads();

    const float* Lb0 = L + (bo + n00) * (size_t)NN + mc;
    int rl = warp * 8;   // group 0's row within tile
    float2 c0 = __ldg((const float2*)(Lb0 + (size_t)rl * NN));
    float2 c1 = __ldg((const float2*)(Lb0 + (size_t)(rl + 1) * NN));

    #pragma unroll 4
    for (int it = 0; it < 16; it++) {
        // prefetch next group (clamped on last iter; redundant L2-hit load)
        const int itn = (it < 15) ? (it + 1) : 15;
        const int rln = ((itn >> 2) << 6) + warp * 8 + ((itn & 3) << 1);
        float2 p0 = __ldg((const float2*)(Lb0 + (size_t)rln * NN));
        float2 p1 = __ldg((const float2*)(Lb0 + (size_t)(rln + 1) * NN));

        // compute current group (rows rl, rl+1)
        const float w0 = wwn_s[rl], w1 = wwn_s[rl + 1];
        const u64 AA  = pack2(1.f - w0, 1.f - w1);
        const u64 WWp = pack2(w0, w1);
        const float4 rnA = rn_s[rl];
        const float4 rnB = rn_s[rl + 1];
        u64 rn_p[4];
        rn_p[0] = pack2(rnA.x, rnB.x); rn_p[1] = pack2(rnA.y, rnB.y);
        rn_p[2] = pack2(rnA.z, rnB.z); rn_p[3] = pack2(rnA.w, rnB.w);
        u64 lv_p[2];
        lv_p[0] = pack2(c0.x, c1.x);
        lv_p[1] = pack2(c0.y, c1.y);

        u64 v_p[4];   // fwd partials per r: (row_even, row_odd)
        {
            const u64 aw0 = add2(AA, negwm_d[0]);
            const u64 t0  = mul2(WWp, pm_d[0]);
            const u64 ap0 = fma2(lv_p[0], aw0, t0);
            #pragma unroll
            for (int r = 0; r < 4; r++) {
                bacc_p[0][r] = fma2(ap0, rn_p[r], bacc_p[0][r]);
                v_p[r] = mul2(ap0, rm_d[0][r]);
            }
            const u64 aw1 = add2(AA, negwm_d[1]);
            const u64 t1  = mul2(WWp, pm_d[1]);
            const u64 ap1 = fma2(lv_p[1], aw1, t1);
            #pragma unroll
            for (int r = 0; r < 4; r++) {
                bacc_p[1][r] = fma2(ap1, rn_p[r], bacc_p[1][r]);
                v_p[r] = fma2(ap1, rm_d[1][r], v_p[r]);
            }
        }

        // packed reduce-scatter: 4 u64 items over 32 lanes
        {
            bool up;
            up = (lane & 16) != 0;
            #pragma unroll
            for (int i = 0; i < 2; i++) {
                u64 send = up ? v_p[i] : v_p[i+2];
                u64 recv = __shfl_xor_sync(0xffffffffu, send, 16);
                v_p[i] = add2(up ? v_p[i+2] : v_p[i], recv);
            }
            up = (lane & 8) != 0;
            {
                u64 send = up ? v_p[0] : v_p[1];
                u64 recv = __shfl_xor_sync(0xffffffffu, send, 8);
                v_p[0] = add2(up ? v_p[1] : v_p[0], recv);
            }
            v_p[0] = add2(v_p[0], __shfl_xor_sync(0xffffffffu, v_p[0], 4));
            v_p[0] = add2(v_p[0], __shfl_xor_sync(0xffffffffu, v_p[0], 2));
            v_p[0] = add2(v_p[0], __shfl_xor_sync(0xffffffffu, v_p[0], 1));
        }
        // lane holds item j = 2*bit4 + bit3 = r ; writers: lane%8 == 0
        if ((lane & 7) == 0) {
            const int r = (((lane >> 4) & 1) << 1) | ((lane >> 3) & 1);
            float lo, hi;
            unpack2(lo, hi, v_p[0]);
            const size_t rowb = bo + n00 + rl;
            atomicAdd(g_fwd + rowb*4 + r,       lo);
            atomicAdd(g_fwd + (rowb + 1)*4 + r, hi);
        }

        c0 = p0; c1 = p1; rl = rln;
    }

    // bwd merge: unpack (even+odd halves), per-warp smem slabs, tree add + RED
    __syncthreads();
    {
        float b0[4], b1[4];
        #pragma unroll
        for (int r = 0; r < 4; r++) {
            float lo, hi;
            unpack2(lo, hi, bacc_p[0][r]); b0[r] = lo + hi;
            unpack2(lo, hi, bacc_p[1][r]); b1[r] = lo + hi;
        }
        *(float4*)&bw_s[warp][lane*2 + 0][0] = make_float4(b0[0], b0[1], b0[2], b0[3]);
        *(float4*)&bw_s[warp][lane*2 + 1][0] = make_float4(b1[0], b1[1], b1[2], b1[3]);
    }
    __syncthreads();
    {
        const int col = tid >> 2, r = tid & 3;   // 256 threads = 64 cols x 4 r
        float s = bw_s[0][col][r] + bw_s[1][col][r] + bw_s[2][col][r] + bw_s[3][col][r]
                + bw_s[4][col][r] + bw_s[5][col][r] + bw_s[6][col][r] + bw_s[7][col][r];
        atomicAdd(g_bwd + (size_t)(bo + m0 + col)*4 + r, s);
    }
}

// ---------------- K7: combine read modes (+ diag correction) + bwr -----------
__global__ void k7_read(const float* __restrict__ read_modes,
                        const float* __restrict__ L,
                        const float* __restrict__ prec,
                        const float* __restrict__ rwo,
                        float* __restrict__ out) {
    const int b   = blockIdx.y;
    const int n0  = blockIdx.x * 256;
    const int tid = threadIdx.x;          // 256
    const int w = tid & 63, r = tid >> 6;
    const size_t bo = (size_t)b * NN;
    __shared__ float rw_s[64][4];
    const int nl = tid >> 2, rr = tid & 3;
    const float mm0 = read_modes[b*12 + rr];
    const float mm1 = read_modes[b*12 + 4 + rr];
    const float mm2 = read_modes[b*12 + 8 + rr];

    float acc = 0.f;
    for (int c = 0; c < 256; c += 64) {
        const int n = n0 + c + nl;
        size_t idx = (bo + n)*4 + rr;
        // diag correction: a_nn = (1-2ww_n)L[n,n] + ww_n p_n ; subtract a_nn*rwo[n,r]
        const float Lnn = L[(bo + n)*(size_t)NN + n];
        const float wwn = g_ww[bo + n];
        const float ann = fmaf(1.f - 2.f*wwn, Lnn, wwn * prec[bo + n]);
        const float corr = ann * rwo[idx];
        float rwv = mm0*(g_bwd[idx] - corr) + mm1*g_cbr[idx] + mm2*(g_fwd[idx] - corr);
        __syncthreads();
        rw_s[nl][rr] = rwv;
        __syncthreads();
        const float* mp = g_memnew + (bo + n0 + c)*WW + w;
        #pragma unroll 8
        for (int q = 0; q < 64; q++)
            acc = fmaf(mp[(size_t)q*WW], rw_s[q][r], acc);
    }
    atomicAdd(&out[b*WW*RR + w*RR + r], acc);
}

// ---------------- launch -----------------------------------------------------
extern "C" void kernel_launch(void* const* d_in, const int* in_sizes, int n_in,
                              void* d_out, int out_size) {
    const float* erase_vector    = (const float*)d_in[0];
    const float* free_gates      = (const float*)d_in[1];
    const float* allocation_gate = (const float*)d_in[2];
    const float* write_gate      = (const float*)d_in[3];
    const float* read_modes      = (const float*)d_in[4];
    const float* read_strengths  = (const float*)d_in[5];
    const float* read_keys       = (const float*)d_in[6];
    const float* write_vector    = (const float*)d_in[7];
    const float* write_key       = (const float*)d_in[8];
    const float* write_strength  = (const float*)d_in[9];
    const float* memory          = (const float*)d_in[10];
    const float* read_weightings = (const float*)d_in[11];
    const float* write_weighting = (const float*)d_in[12];
    const float* memory_usage    = (const float*)d_in[13];
    const float* link_matrix     = (const float*)d_in[14];
    const float* precedence      = (const float*)d_in[15];
    float* out = (float*)d_out;

    k1_usage_sim<<<dim3(16, 8), 256>>>(memory, write_key, write_strength, free_gates,
                                       read_weightings, write_weighting, memory_usage, out);
    k2_alloc<<<8, 1024>>>();
    k3_ww<<<8, 1024>>>(allocation_gate, write_gate);
    // k6 at launch index 3 so ncu's fixed-skip capture lands on it
    k6_link<<<dim3(NN/K6_TM, NN/K6_ROWS, BB), 256>>>(link_matrix, read_weightings, precedence);
    k4_memupdate<<<dim3(16, 8), 256>>>(memory, erase_vector, write_vector,
                                       read_keys, read_strengths);
    k5_cbr<<<dim3(4, 8), 256>>>();
    k7_read<<<dim3(16, 8), 256>>>(read_modes, link_matrix, precedence, read_weightings, out);
}